// round 2
// baseline (speedup 1.0000x reference)
#include <cuda_runtime.h>
#include <math.h>

// ----------------- problem constants -----------------
constexpr int kT    = 2048;
constexpr int kH    = 4096;
constexpr int kNH   = 32;
constexpr int kNKV  = 8;
constexpr int kHD   = 128;
constexpr int kQKV  = 6144;   // Q_SIZE + 2*KV_SIZE
constexpr int kQS   = 4096;   // Q_SIZE
constexpr int kKOff = 4096;   // k column offset inside qkv
constexpr int kVOff = 5120;   // v column offset inside qkv

// ----------------- scratch (no allocations allowed) -----------------
__device__ float g_qkv[kT * kQKV];   // qkv projection (rope applied in place)
__device__ float g_attn[kT * kQS];   // attention output before o-proj

// ----------------- packed fp32x2 helpers -----------------
__device__ __forceinline__ void ffma2(unsigned long long &d, unsigned long long a,
                                      unsigned long long b) {
  asm("fma.rn.f32x2 %0, %1, %2, %0;" : "+l"(d) : "l"(a), "l"(b));
}
__device__ __forceinline__ float f2lo(unsigned long long v) {
  return __uint_as_float((unsigned)(v & 0xffffffffull));
}
__device__ __forceinline__ float f2hi(unsigned long long v) {
  return __uint_as_float((unsigned)(v >> 32));
}

// =====================================================================
// SGEMM: C[M,N] = A[M,K] @ B[K,N].  Block tile 128x128, k-tile 16,
// 256 threads, double-buffered smem, packed f32x2 FFMA.
// Thread (tx=tid&15, ty=tid>>4) computes rows {4ty+i, 64+4ty+i} (i<4)
// and cols {4tx+j, 64+4tx+j} (j<4).
// A is stored DUPLICATED in smem: As2[k][2m],As2[k][2m+1] = A[m][k], so a
// single LDS.128 yields two packed (a,a) 64-bit operands.
// =====================================================================
template <int N, int K>
__device__ __forceinline__ void gemm_body(const float* __restrict__ A,
                                          const float* __restrict__ B,
                                          float* __restrict__ C) {
  __shared__ float As2[2][16][256];   // 32 KB
  __shared__ float Bs[2][16][128];    // 16 KB

  const int tid = threadIdx.x;
  const int tx = tid & 15, ty = tid >> 4;
  const int m0 = blockIdx.y << 7;
  const int n0 = blockIdx.x << 7;

  // A loader mapping: row ar (+64), cols ak..ak+3 of the k-tile
  const int ar = tid >> 2;          // 0..63
  const int ak = (tid & 3) << 2;    // 0,4,8,12
  // B loader mapping: k-row br (+8), cols bc..bc+3
  const int br = tid >> 5;          // 0..7
  const int bc = (tid & 31) << 2;   // 0..124

  const float* Ag0 = A + (size_t)(m0 + ar) * K + ak;
  const float* Ag1 = Ag0 + (size_t)64 * K;
  const float* Bg0 = B + (size_t)br * N + n0 + bc;
  const float* Bg1 = Bg0 + (size_t)8 * N;

  unsigned long long acc[8][4];
#pragma unroll
  for (int a = 0; a < 8; ++a)
#pragma unroll
    for (int p = 0; p < 4; ++p) acc[a][p] = 0ull;

  // ---- prologue: stage k-tile 0 into buffer 0 ----
  {
    float4 a0 = *(const float4*)Ag0;
    float4 a1 = *(const float4*)Ag1;
    float4 b0 = *(const float4*)Bg0;
    float4 b1 = *(const float4*)Bg1;
#pragma unroll
    for (int kk = 0; kk < 4; ++kk) {
      float v0 = (&a0.x)[kk], v1 = (&a1.x)[kk];
      *(float2*)&As2[0][ak + kk][2 * ar]       = make_float2(v0, v0);
      *(float2*)&As2[0][ak + kk][128 + 2 * ar] = make_float2(v1, v1);
    }
    *(float4*)&Bs[0][br][bc]     = b0;
    *(float4*)&Bs[0][br + 8][bc] = b1;
  }
  __syncthreads();

  constexpr int nk = K / 16;
  int buf = 0;
#pragma unroll 1
  for (int kt = 0; kt < nk; ++kt) {
    float4 a0, a1, b0, b1;
    const bool more = (kt + 1 < nk);
    if (more) {  // prefetch next k-tile into registers
      const float* ap = Ag0 + (kt + 1) * 16;
      a0 = *(const float4*)ap;
      a1 = *(const float4*)(ap + (size_t)64 * K);
      const float* bp = Bg0 + (size_t)(kt + 1) * 16 * N;
      b0 = *(const float4*)bp;
      b1 = *(const float4*)(bp + (size_t)8 * N);
    }
#pragma unroll
    for (int k = 0; k < 16; ++k) {
      const ulonglong2 B0 = *(const ulonglong2*)&Bs[buf][k][4 * tx];
      const ulonglong2 B1 = *(const ulonglong2*)&Bs[buf][k][64 + 4 * tx];
      const ulonglong2 A0 = *(const ulonglong2*)&As2[buf][k][8 * ty];
      const ulonglong2 A1 = *(const ulonglong2*)&As2[buf][k][8 * ty + 4];
      const ulonglong2 A2 = *(const ulonglong2*)&As2[buf][k][128 + 8 * ty];
      const ulonglong2 A3 = *(const ulonglong2*)&As2[buf][k][128 + 8 * ty + 4];
      const unsigned long long aa[8] = {A0.x, A0.y, A1.x, A1.y,
                                        A2.x, A2.y, A3.x, A3.y};
#pragma unroll
      for (int a = 0; a < 8; ++a) {
        ffma2(acc[a][0], aa[a], B0.x);
        ffma2(acc[a][1], aa[a], B0.y);
        ffma2(acc[a][2], aa[a], B1.x);
        ffma2(acc[a][3], aa[a], B1.y);
      }
    }
    if (more) {
      const int nb = buf ^ 1;
#pragma unroll
      for (int kk = 0; kk < 4; ++kk) {
        float v0 = (&a0.x)[kk], v1 = (&a1.x)[kk];
        *(float2*)&As2[nb][ak + kk][2 * ar]       = make_float2(v0, v0);
        *(float2*)&As2[nb][ak + kk][128 + 2 * ar] = make_float2(v1, v1);
      }
      *(float4*)&Bs[nb][br][bc]     = b0;
      *(float4*)&Bs[nb][br + 8][bc] = b1;
      buf = nb;
    }
    __syncthreads();
  }

  // ---- epilogue ----
#pragma unroll
  for (int a = 0; a < 8; ++a) {
    const int row = m0 + ((a < 4) ? (4 * ty + a) : (64 + 4 * ty + (a - 4)));
    float* Cp = C + (size_t)row * N + n0;
    float4 o0, o1;
    o0.x = f2lo(acc[a][0]); o0.y = f2hi(acc[a][0]);
    o0.z = f2lo(acc[a][1]); o0.w = f2hi(acc[a][1]);
    o1.x = f2lo(acc[a][2]); o1.y = f2hi(acc[a][2]);
    o1.z = f2lo(acc[a][3]); o1.w = f2hi(acc[a][3]);
    *(float4*)(Cp + 4 * tx)      = o0;
    *(float4*)(Cp + 64 + 4 * tx) = o1;
  }
}

__global__ __launch_bounds__(256, 2)
void gemm_qkv_kernel(const float* __restrict__ hidden,
                     const float* __restrict__ wqkv) {
  gemm_body<kQKV, kH>(hidden, wqkv, g_qkv);
}

__global__ __launch_bounds__(256, 2)
void gemm_out_kernel(const float* __restrict__ wo, float* __restrict__ out) {
  gemm_body<kH, kQS>(g_attn, wo, out);
}

// =====================================================================
// RoPE in place on the q and k regions of g_qkv.
// One thread per (token, head, pair i<64): rotates (x[i], x[i+64]).
// =====================================================================
__global__ void rope_kernel(const int* __restrict__ pos) {
  const int idx = blockIdx.x * blockDim.x + threadIdx.x;
  const int totq = kT * kNH * 64;
  const int tot  = totq + kT * kNKV * 64;
  if (idx >= tot) return;

  float* base;
  int t, i;
  if (idx < totq) {
    t = idx / (kNH * 64);
    const int r = idx - t * (kNH * 64);
    i = r & 63;
    base = g_qkv + (size_t)t * kQKV + (r >> 6) * kHD;
  } else {
    const int j = idx - totq;
    t = j / (kNKV * 64);
    const int r = j - t * (kNKV * 64);
    i = r & 63;
    base = g_qkv + (size_t)t * kQKV + kKOff + (r >> 6) * kHD;
  }
  const float inv = (float)pow(500000.0, -(double)i / 64.0);
  const float f = (float)pos[t] * inv;   // fp32 product, like the reference
  float sn, cs;
  sincosf(f, &sn, &cs);
  const float x1 = base[i], x2 = base[i + 64];
  base[i]      = x1 * cs - x2 * sn;
  base[i + 64] = x2 * cs + x1 * sn;
}

// =====================================================================
// Flash attention, fp32, BQ = BS = 64, GQA group = 4. 256 threads.
// smem: Q/K/V tiles 64x128 (XOR-swizzled float4 slots) + P tile 64x64.
// Swizzle slot(r,c4) = c4 ^ ((r>>2)&7) ^ ((r&3)<<3):
//   - tile fill (r fixed per 32 lanes, c4 = lane)         -> conflict-free
//   - GEMM1 K reads (rows 4tx+j, d4 fixed)                -> conflict-free
//   - GEMM1 Q reads (2 distinct addresses, broadcast)     -> conflict-free
//   - GEMM2 V reads (row fixed, c4 = tx / 16+tx)          -> conflict-free
// =====================================================================
__device__ __forceinline__ int swz(int r, int c4) {
  return c4 ^ ((r >> 2) & 7) ^ ((r & 3) << 3);
}

__global__ __launch_bounds__(256)
void attn_kernel() {
  extern __shared__ float sm[];
  float* sQ = sm;              // 64*128
  float* sK = sm + 8192;       // 64*128
  float* sV = sm + 16384;      // 64*128
  float* sP = sm + 24576;      // 64*64

  const int h   = blockIdx.x;
  const int qb  = (int)gridDim.y - 1 - (int)blockIdx.y;  // heavy blocks first
  const int kvh = h >> 2;
  const int tid = threadIdx.x;
  const int tx = tid & 15, ty = tid >> 4;
  const int q0 = qb << 6;

  const float scale = 0.08838834764831845f;  // 1/sqrt(128)

  // ---- load Q tile (pre-scaled) ----
  {
    const float* Qg = g_qkv + (size_t)q0 * kQKV + h * kHD;
#pragma unroll
    for (int it = 0; it < 8; ++it) {
      const int idx = tid + (it << 8);
      const int r = idx >> 5, c4 = idx & 31;
      float4 v = *(const float4*)(Qg + (size_t)r * kQKV + (c4 << 2));
      v.x *= scale; v.y *= scale; v.z *= scale; v.w *= scale;
      *(float4*)(sQ + (r << 7) + (swz(r, c4) << 2)) = v;
    }
  }

  float o[4][8];
  float mrun[4], lrun[4];
#pragma unroll
  for (int i = 0; i < 4; ++i) {
    mrun[i] = -1e30f; lrun[i] = 0.f;
#pragma unroll
    for (int c = 0; c < 8; ++c) o[i][c] = 0.f;
  }

  // precomputed swizzle constants for this thread's rows
  int qswz[4], kswz[4];
#pragma unroll
  for (int i = 0; i < 4; ++i) {
    const int rq = 4 * ty + i;
    qswz[i] = ((rq >> 2) & 7) ^ ((rq & 3) << 3);
    const int rk = 4 * tx + i;
    kswz[i] = ((rk >> 2) & 7) ^ ((rk & 3) << 3);
  }
  __syncthreads();

  const int nblk = qb + 1;
  for (int b = 0; b < nblk; ++b) {
    const int s0 = b << 6;
    // ---- load K, V tiles ----
    const float* Kg = g_qkv + (size_t)s0 * kQKV + kKOff + kvh * kHD;
    const float* Vg = g_qkv + (size_t)s0 * kQKV + kVOff + kvh * kHD;
#pragma unroll
    for (int it = 0; it < 8; ++it) {
      const int idx = tid + (it << 8);
      const int r = idx >> 5, c4 = idx & 31;
      const int so = (r << 7) + (swz(r, c4) << 2);
      *(float4*)(sK + so) = *(const float4*)(Kg + (size_t)r * kQKV + (c4 << 2));
      *(float4*)(sV + so) = *(const float4*)(Vg + (size_t)r * kQKV + (c4 << 2));
    }
    __syncthreads();

    // ---- GEMM1: s[i][j] = sum_d Q[4ty+i][d] * K[4tx+j][d] ----
    float s[4][4];
#pragma unroll
    for (int i = 0; i < 4; ++i)
#pragma unroll
      for (int j = 0; j < 4; ++j) s[i][j] = 0.f;

#pragma unroll 8
    for (int d4 = 0; d4 < 32; ++d4) {
      float4 qv[4], kv[4];
#pragma unroll
      for (int i = 0; i < 4; ++i)
        qv[i] = *(const float4*)(sQ + ((4 * ty + i) << 7) + ((d4 ^ qswz[i]) << 2));
#pragma unroll
      for (int j = 0; j < 4; ++j)
        kv[j] = *(const float4*)(sK + ((4 * tx + j) << 7) + ((d4 ^ kswz[j]) << 2));
#pragma unroll
      for (int i = 0; i < 4; ++i)
#pragma unroll
        for (int j = 0; j < 4; ++j)
          s[i][j] += qv[i].x * kv[j].x + qv[i].y * kv[j].y +
                     qv[i].z * kv[j].z + qv[i].w * kv[j].w;
    }

    // ---- causal mask (diagonal block only) ----
    if (s0 == q0) {
#pragma unroll
      for (int i = 0; i < 4; ++i)
#pragma unroll
        for (int j = 0; j < 4; ++j)
          if (4 * tx + j > 4 * ty + i) s[i][j] = -1e30f;
    }

    // ---- online softmax (row stats reduced over the 16 tx lanes) ----
#pragma unroll
    for (int i = 0; i < 4; ++i) {
      float mx = fmaxf(fmaxf(s[i][0], s[i][1]), fmaxf(s[i][2], s[i][3]));
#pragma unroll
      for (int w = 1; w < 16; w <<= 1)
        mx = fmaxf(mx, __shfl_xor_sync(0xffffffffu, mx, w));
      const float mnew = fmaxf(mrun[i], mx);
      const float fac = __expf(mrun[i] - mnew);
      float rs = 0.f;
#pragma unroll
      for (int j = 0; j < 4; ++j) {
        s[i][j] = __expf(s[i][j] - mnew);
        rs += s[i][j];
      }
#pragma unroll
      for (int w = 1; w < 16; w <<= 1)
        rs += __shfl_xor_sync(0xffffffffu, rs, w);
      lrun[i] = lrun[i] * fac + rs;
      mrun[i] = mnew;
#pragma unroll
      for (int c = 0; c < 8; ++c) o[i][c] *= fac;
    }

    // ---- stage P ----
#pragma unroll
    for (int i = 0; i < 4; ++i)
      *(float4*)(sP + ((4 * ty + i) << 6) + 4 * tx) =
          make_float4(s[i][0], s[i][1], s[i][2], s[i][3]);
    __syncthreads();

    // ---- GEMM2: o[i][c] += sum_s P[4ty+i][s] * V[s][col(c)] ----
#pragma unroll 4
    for (int s4 = 0; s4 < 16; ++s4) {
      float4 p4[4];
#pragma unroll
      for (int i = 0; i < 4; ++i)
        p4[i] = *(const float4*)(sP + ((4 * ty + i) << 6) + (s4 << 2));
#pragma unroll
      for (int u = 0; u < 4; ++u) {
        const int srow = (s4 << 2) + u;
        const int sw = ((srow >> 2) & 7) ^ ((srow & 3) << 3);
        const float4 v0 = *(const float4*)(sV + (srow << 7) + ((tx ^ sw) << 2));
        const float4 v1 = *(const float4*)(sV + (srow << 7) + (((16 + tx) ^ sw) << 2));
#pragma unroll
        for (int i = 0; i < 4; ++i) {
          const float pv = (&p4[i].x)[u];
          o[i][0] += pv * v0.x; o[i][1] += pv * v0.y;
          o[i][2] += pv * v0.z; o[i][3] += pv * v0.w;
          o[i][4] += pv * v1.x; o[i][5] += pv * v1.y;
          o[i][6] += pv * v1.z; o[i][7] += pv * v1.w;
        }
      }
    }
    __syncthreads();
  }

  // ---- epilogue: normalize and write ----
  float* Og = g_attn + (size_t)q0 * kQS + h * kHD;
#pragma unroll
  for (int i = 0; i < 4; ++i) {
    const float inv = 1.0f / lrun[i];
    float* row = Og + (size_t)(4 * ty + i) * kQS;
    *(float4*)(row + 4 * tx) =
        make_float4(o[i][0] * inv, o[i][1] * inv, o[i][2] * inv, o[i][3] * inv);
    *(float4*)(row + 64 + 4 * tx) =
        make_float4(o[i][4] * inv, o[i][5] * inv, o[i][6] * inv, o[i][7] * inv);
  }
}

// =====================================================================
// launch
// =====================================================================
extern "C" void kernel_launch(void* const* d_in, const int* in_sizes, int n_in,
                              void* d_out, int out_size) {
  const int*   positions = (const int*)d_in[0];
  const float* hidden    = (const float*)d_in[1];
  const float* wqkv      = (const float*)d_in[2];
  const float* wo        = (const float*)d_in[3];
  float*       out       = (float*)d_out;

  constexpr int kAttnSmem = (3 * 64 * 128 + 64 * 64) * 4;  // 114688 B
  cudaFuncSetAttribute(attn_kernel, cudaFuncAttributeMaxDynamicSharedMemorySize,
                       kAttnSmem);

  gemm_qkv_kernel<<<dim3(kQKV / 128, kT / 128), 256>>>(hidden, wqkv);

  const int ropeTot = kT * (kNH + kNKV) * 64;
  rope_kernel<<<(ropeTot + 255) / 256, 256>>>(positions);

  attn_kernel<<<dim3(kNH, kT / 64), 256, kAttnSmem>>>();

  gemm_out_kernel<<<dim3(kQS / 128, kT / 128), 256>>>(wo, out);
}

// round 6
// speedup vs baseline: 1.6612x; 1.6612x over previous
#include <cuda_runtime.h>
#include <cuda_bf16.h>
#include <math.h>
#include <stdint.h>

// ----------------- problem constants -----------------
constexpr int kT    = 2048;
constexpr int kH    = 4096;
constexpr int kNH   = 32;
constexpr int kNKV  = 8;
constexpr int kHD   = 128;
constexpr int kQKV  = 6144;
constexpr int kQS   = 4096;
constexpr int kKOff = 4096;
constexpr int kVOff = 5120;

// ----------------- scratch (no allocations allowed) -----------------
__device__ float g_qkv[kT * kQKV];
__device__ float g_attn[kT * kQS];
__device__ __align__(16) __nv_bfloat16 g_ah[kT * kH];     // A hi (both gemms)
__device__ __align__(16) __nv_bfloat16 g_al[kT * kH];     // A lo
__device__ __align__(16) __nv_bfloat16 g_b1h[kQKV * kH];  // w_qkv^T hi [N,K]
__device__ __align__(16) __nv_bfloat16 g_b1l[kQKV * kH];
__device__ __align__(16) __nv_bfloat16 g_b2h[kQS * kH];   // w_o^T hi [N,K]
__device__ __align__(16) __nv_bfloat16 g_b2l[kQS * kH];

// ================= low-level helpers =================
__device__ __forceinline__ uint32_t smem_u32(const void* p) {
  uint32_t a;
  asm("{ .reg .u64 t; cvta.to.shared.u64 t, %1; cvt.u32.u64 %0, t; }"
      : "=r"(a) : "l"(p));
  return a;
}
__device__ __forceinline__ void ldsm4(uint32_t* r, uint32_t addr) {
  asm volatile("ldmatrix.sync.aligned.m8n8.x4.shared.b16 {%0,%1,%2,%3}, [%4];"
               : "=r"(r[0]), "=r"(r[1]), "=r"(r[2]), "=r"(r[3]) : "r"(addr));
}
__device__ __forceinline__ void mma_bf16(float* c, const uint32_t* a,
                                         uint32_t b0, uint32_t b1) {
  asm volatile(
      "mma.sync.aligned.m16n8k16.row.col.f32.bf16.bf16.f32 "
      "{%0,%1,%2,%3}, {%4,%5,%6,%7}, {%8,%9}, {%0,%1,%2,%3};"
      : "+f"(c[0]), "+f"(c[1]), "+f"(c[2]), "+f"(c[3])
      : "r"(a[0]), "r"(a[1]), "r"(a[2]), "r"(a[3]), "r"(b0), "r"(b1));
}

// =====================================================================
// Conversion kernels
// =====================================================================
__global__ void split_kernel(const float* __restrict__ X,
                             __nv_bfloat16* __restrict__ H,
                             __nv_bfloat16* __restrict__ L, int total4) {
  const int i = blockIdx.x * blockDim.x + threadIdx.x;
  if (i >= total4) return;
  const float4 v = ((const float4*)X)[i];
  __nv_bfloat16 hx = __float2bfloat16_rn(v.x);
  __nv_bfloat16 hy = __float2bfloat16_rn(v.y);
  __nv_bfloat16 hz = __float2bfloat16_rn(v.z);
  __nv_bfloat16 hw = __float2bfloat16_rn(v.w);
  __nv_bfloat162* Hp = (__nv_bfloat162*)H;
  Hp[2 * i]     = __nv_bfloat162(hx, hy);
  Hp[2 * i + 1] = __nv_bfloat162(hz, hw);
  __nv_bfloat162* Lp = (__nv_bfloat162*)L;
  Lp[2 * i] = __nv_bfloat162(__float2bfloat16_rn(v.x - __bfloat162float(hx)),
                             __float2bfloat16_rn(v.y - __bfloat162float(hy)));
  Lp[2 * i + 1] = __nv_bfloat162(__float2bfloat16_rn(v.z - __bfloat162float(hz)),
                                 __float2bfloat16_rn(v.w - __bfloat162float(hw)));
}

// W[K,N] fp32 -> Th/Tl[N,K] bf16 (transpose + split)
__global__ void transpose_split_kernel(const float* __restrict__ W,
                                       __nv_bfloat16* __restrict__ Th,
                                       __nv_bfloat16* __restrict__ Tl,
                                       int K, int N) {
  __shared__ float t[32][33];
  const int n0 = blockIdx.x * 32, k0 = blockIdx.y * 32;
  const int tx = threadIdx.x, ty = threadIdx.y;
#pragma unroll
  for (int j = 0; j < 4; ++j)
    t[ty + 8 * j][tx] = W[(size_t)(k0 + ty + 8 * j) * N + n0 + tx];
  __syncthreads();
#pragma unroll
  for (int j = 0; j < 4; ++j) {
    const int n = ty + 8 * j;
    const float v = t[tx][n];
    const __nv_bfloat16 h = __float2bfloat16_rn(v);
    const size_t o = (size_t)(n0 + n) * K + k0 + tx;
    Th[o] = h;
    Tl[o] = __float2bfloat16_rn(v - __bfloat162float(h));
  }
}

// =====================================================================
// bf16x3 GEMM on mma.sync (HMMA). C[M,NT] = A[M,4096] @ B^T[N,K].
// Block 128x128, BK=32, 8 warps (2x4), warp tile 64x32.
// Static smem, single stage, register-prefetch double buffering.
// Rows padded to 40 halves (80B) -> conflict-free ldmatrix, 16B aligned.
// =====================================================================
constexpr int kLds = 40;  // halves per smem row

__global__ __launch_bounds__(256)
void gemm_mma_kernel(const __nv_bfloat16* __restrict__ Ah,
                     const __nv_bfloat16* __restrict__ Al,
                     const __nv_bfloat16* __restrict__ Bh,
                     const __nv_bfloat16* __restrict__ Bl,
                     float* __restrict__ C, int NT) {
  constexpr int K = kH;        // 4096
  constexpr int BK = 32;
  constexpr int NST = K / BK;  // 128
  constexpr int TILE = 128 * kLds;  // halves per tile
  __shared__ __align__(16) __nv_bfloat16 smem[4 * TILE];  // 40960 B

  const int tid = threadIdx.x;
  const int wid = tid >> 5, lane = tid & 31;
  const int m0 = blockIdx.y << 7;
  const int n0 = blockIdx.x << 7;
  const int wm = (wid >> 2) << 6;  // 0/64
  const int wn = (wid & 3) << 5;   // 0/32/64/96

  const int lr = tid >> 2, ls = tid & 3;
  const uint32_t base = smem_u32(smem);

  float acc[4][4][4];
#pragma unroll
  for (int i = 0; i < 4; ++i)
#pragma unroll
    for (int j = 0; j < 4; ++j)
#pragma unroll
      for (int q = 0; q < 4; ++q) acc[i][j][q] = 0.f;

  const size_t aOff0 = (size_t)(m0 + lr) * K + ls * 8;
  const size_t aOff1 = aOff0 + (size_t)64 * K;
  const size_t bOff0 = (size_t)(n0 + lr) * K + ls * 8;
  const size_t bOff1 = bOff0 + (size_t)64 * K;

  // register staging for the next k-chunk
  uint4 rAh0, rAh1, rAl0, rAl1, rBh0, rBh1, rBl0, rBl1;
  rAh0 = *(const uint4*)(Ah + aOff0);
  rAh1 = *(const uint4*)(Ah + aOff1);
  rAl0 = *(const uint4*)(Al + aOff0);
  rAl1 = *(const uint4*)(Al + aOff1);
  rBh0 = *(const uint4*)(Bh + bOff0);
  rBh1 = *(const uint4*)(Bh + bOff1);
  rBl0 = *(const uint4*)(Bl + bOff0);
  rBl1 = *(const uint4*)(Bl + bOff1);

  const int s0 = lr * kLds + ls * 8;         // halves
  const int s1 = (lr + 64) * kLds + ls * 8;

#pragma unroll 1
  for (int kt = 0; kt < NST; ++kt) {
    __syncthreads();  // previous compute finished before overwrite
    *(uint4*)&smem[s0]            = rAh0;
    *(uint4*)&smem[s1]            = rAh1;
    *(uint4*)&smem[TILE + s0]     = rAl0;
    *(uint4*)&smem[TILE + s1]     = rAl1;
    *(uint4*)&smem[2 * TILE + s0] = rBh0;
    *(uint4*)&smem[2 * TILE + s1] = rBh1;
    *(uint4*)&smem[3 * TILE + s0] = rBl0;
    *(uint4*)&smem[3 * TILE + s1] = rBl1;
    __syncthreads();

    if (kt + 1 < NST) {  // prefetch next chunk (overlaps with compute below)
      const int kc = (kt + 1) * BK;
      rAh0 = *(const uint4*)(Ah + aOff0 + kc);
      rAh1 = *(const uint4*)(Ah + aOff1 + kc);
      rAl0 = *(const uint4*)(Al + aOff0 + kc);
      rAl1 = *(const uint4*)(Al + aOff1 + kc);
      rBh0 = *(const uint4*)(Bh + bOff0 + kc);
      rBh1 = *(const uint4*)(Bh + bOff1 + kc);
      rBl0 = *(const uint4*)(Bl + bOff0 + kc);
      rBl1 = *(const uint4*)(Bl + bOff1 + kc);
    }

#pragma unroll
    for (int kh = 0; kh < 2; ++kh) {
      const int slot = kh * 2 + (lane >> 4);   // 0..3
      const int arow = wm + (lane & 15);
      const int brow = wn + (lane & 15);

      uint32_t ah[4][4], al[4][4];
#pragma unroll
      for (int i = 0; i < 4; ++i) {
        const uint32_t ad = base + (uint32_t)(((arow + 16 * i) * kLds + slot * 8) * 2);
        ldsm4(ah[i], ad);
        ldsm4(al[i], ad + TILE * 2);
      }
      uint32_t bh[2][4], bl[2][4];
#pragma unroll
      for (int p = 0; p < 2; ++p) {
        const uint32_t bd = base + (uint32_t)(2 * TILE * 2) +
                            (uint32_t)(((brow + 16 * p) * kLds + slot * 8) * 2);
        ldsm4(bh[p], bd);
        ldsm4(bl[p], bd + TILE * 2);
      }
#pragma unroll
      for (int i = 0; i < 4; ++i)
#pragma unroll
        for (int j = 0; j < 4; ++j) {
          const int p = j >> 1, w = j & 1;
          mma_bf16(acc[i][j], ah[i], bh[p][w], bh[p][2 + w]);
          mma_bf16(acc[i][j], ah[i], bl[p][w], bl[p][2 + w]);
          mma_bf16(acc[i][j], al[i], bh[p][w], bh[p][2 + w]);
        }
    }
  }

  // ---- epilogue ----
  const int g = lane >> 2, t4 = lane & 3;
#pragma unroll
  for (int i = 0; i < 4; ++i) {
    const int r0 = m0 + wm + 16 * i + g;
#pragma unroll
    for (int j = 0; j < 4; ++j) {
      const int col = n0 + wn + 8 * j + 2 * t4;
      *(float2*)(C + (size_t)r0 * NT + col) =
          make_float2(acc[i][j][0], acc[i][j][1]);
      *(float2*)(C + (size_t)(r0 + 8) * NT + col) =
          make_float2(acc[i][j][2], acc[i][j][3]);
    }
  }
}

// =====================================================================
// RoPE (unchanged, proven)
// =====================================================================
__global__ void rope_kernel(const int* __restrict__ pos) {
  const int idx = blockIdx.x * blockDim.x + threadIdx.x;
  const int totq = kT * kNH * 64;
  const int tot = totq + kT * kNKV * 64;
  if (idx >= tot) return;

  float* base;
  int t, i;
  if (idx < totq) {
    t = idx / (kNH * 64);
    const int r = idx - t * (kNH * 64);
    i = r & 63;
    base = g_qkv + (size_t)t * kQKV + (r >> 6) * kHD;
  } else {
    const int j = idx - totq;
    t = j / (kNKV * 64);
    const int r = j - t * (kNKV * 64);
    i = r & 63;
    base = g_qkv + (size_t)t * kQKV + kKOff + (r >> 6) * kHD;
  }
  const float inv = (float)pow(500000.0, -(double)i / 64.0);
  const float f = (float)pos[t] * inv;
  float sn, cs;
  sincosf(f, &sn, &cs);
  const float x1 = base[i], x2 = base[i + 64];
  base[i] = x1 * cs - x2 * sn;
  base[i + 64] = x2 * cs + x1 * sn;
}

// =====================================================================
// Flash attention fp32 (unchanged, proven in round 2)
// =====================================================================
__device__ __forceinline__ int swz(int r, int c4) {
  return c4 ^ ((r >> 2) & 7) ^ ((r & 3) << 3);
}

__global__ __launch_bounds__(256)
void attn_kernel() {
  extern __shared__ float sm[];
  float* sQ = sm;
  float* sK = sm + 8192;
  float* sV = sm + 16384;
  float* sP = sm + 24576;

  const int h = blockIdx.x;
  const int qb = (int)gridDim.y - 1 - (int)blockIdx.y;
  const int kvh = h >> 2;
  const int tid = threadIdx.x;
  const int tx = tid & 15, ty = tid >> 4;
  const int q0 = qb << 6;

  const float scale = 0.08838834764831845f;

  {
    const float* Qg = g_qkv + (size_t)q0 * kQKV + h * kHD;
#pragma unroll
    for (int it = 0; it < 8; ++it) {
      const int idx = tid + (it << 8);
      const int r = idx >> 5, c4 = idx & 31;
      float4 v = *(const float4*)(Qg + (size_t)r * kQKV + (c4 << 2));
      v.x *= scale; v.y *= scale; v.z *= scale; v.w *= scale;
      *(float4*)(sQ + (r << 7) + (swz(r, c4) << 2)) = v;
    }
  }

  float o[4][8];
  float mrun[4], lrun[4];
#pragma unroll
  for (int i = 0; i < 4; ++i) {
    mrun[i] = -1e30f; lrun[i] = 0.f;
#pragma unroll
    for (int c = 0; c < 8; ++c) o[i][c] = 0.f;
  }

  int qswz[4], kswz[4];
#pragma unroll
  for (int i = 0; i < 4; ++i) {
    const int rq = 4 * ty + i;
    qswz[i] = ((rq >> 2) & 7) ^ ((rq & 3) << 3);
    const int rk = 4 * tx + i;
    kswz[i] = ((rk >> 2) & 7) ^ ((rk & 3) << 3);
  }
  __syncthreads();

  const int nblk = qb + 1;
  for (int b = 0; b < nblk; ++b) {
    const int s0 = b << 6;
    const float* Kg = g_qkv + (size_t)s0 * kQKV + kKOff + kvh * kHD;
    const float* Vg = g_qkv + (size_t)s0 * kQKV + kVOff + kvh * kHD;
#pragma unroll
    for (int it = 0; it < 8; ++it) {
      const int idx = tid + (it << 8);
      const int r = idx >> 5, c4 = idx & 31;
      const int so = (r << 7) + (swz(r, c4) << 2);
      *(float4*)(sK + so) = *(const float4*)(Kg + (size_t)r * kQKV + (c4 << 2));
      *(float4*)(sV + so) = *(const float4*)(Vg + (size_t)r * kQKV + (c4 << 2));
    }
    __syncthreads();

    float s[4][4];
#pragma unroll
    for (int i = 0; i < 4; ++i)
#pragma unroll
      for (int j = 0; j < 4; ++j) s[i][j] = 0.f;

#pragma unroll 8
    for (int d4 = 0; d4 < 32; ++d4) {
      float4 qv[4], kv[4];
#pragma unroll
      for (int i = 0; i < 4; ++i)
        qv[i] = *(const float4*)(sQ + ((4 * ty + i) << 7) + ((d4 ^ qswz[i]) << 2));
#pragma unroll
      for (int j = 0; j < 4; ++j)
        kv[j] = *(const float4*)(sK + ((4 * tx + j) << 7) + ((d4 ^ kswz[j]) << 2));
#pragma unroll
      for (int i = 0; i < 4; ++i)
#pragma unroll
        for (int j = 0; j < 4; ++j)
          s[i][j] += qv[i].x * kv[j].x + qv[i].y * kv[j].y +
                     qv[i].z * kv[j].z + qv[i].w * kv[j].w;
    }

    if (s0 == q0) {
#pragma unroll
      for (int i = 0; i < 4; ++i)
#pragma unroll
        for (int j = 0; j < 4; ++j)
          if (4 * tx + j > 4 * ty + i) s[i][j] = -1e30f;
    }

#pragma unroll
    for (int i = 0; i < 4; ++i) {
      float mx = fmaxf(fmaxf(s[i][0], s[i][1]), fmaxf(s[i][2], s[i][3]));
#pragma unroll
      for (int w = 1; w < 16; w <<= 1)
        mx = fmaxf(mx, __shfl_xor_sync(0xffffffffu, mx, w));
      const float mnew = fmaxf(mrun[i], mx);
      const float fac = __expf(mrun[i] - mnew);
      float rs = 0.f;
#pragma unroll
      for (int j = 0; j < 4; ++j) {
        s[i][j] = __expf(s[i][j] - mnew);
        rs += s[i][j];
      }
#pragma unroll
      for (int w = 1; w < 16; w <<= 1)
        rs += __shfl_xor_sync(0xffffffffu, rs, w);
      lrun[i] = lrun[i] * fac + rs;
      mrun[i] = mnew;
#pragma unroll
      for (int c = 0; c < 8; ++c) o[i][c] *= fac;
    }

#pragma unroll
    for (int i = 0; i < 4; ++i)
      *(float4*)(sP + ((4 * ty + i) << 6) + 4 * tx) =
          make_float4(s[i][0], s[i][1], s[i][2], s[i][3]);
    __syncthreads();

#pragma unroll 4
    for (int s4 = 0; s4 < 16; ++s4) {
      float4 p4[4];
#pragma unroll
      for (int i = 0; i < 4; ++i)
        p4[i] = *(const float4*)(sP + ((4 * ty + i) << 6) + (s4 << 2));
#pragma unroll
      for (int u = 0; u < 4; ++u) {
        const int srow = (s4 << 2) + u;
        const int sw = ((srow >> 2) & 7) ^ ((srow & 3) << 3);
        const float4 v0 = *(const float4*)(sV + (srow << 7) + ((tx ^ sw) << 2));
        const float4 v1 = *(const float4*)(sV + (srow << 7) + (((16 + tx) ^ sw) << 2));
#pragma unroll
        for (int i = 0; i < 4; ++i) {
          const float pv = (&p4[i].x)[u];
          o[i][0] += pv * v0.x; o[i][1] += pv * v0.y;
          o[i][2] += pv * v0.z; o[i][3] += pv * v0.w;
          o[i][4] += pv * v1.x; o[i][5] += pv * v1.y;
          o[i][6] += pv * v1.z; o[i][7] += pv * v1.w;
        }
      }
    }
    __syncthreads();
  }

  float* Og = g_attn + (size_t)q0 * kQS + h * kHD;
#pragma unroll
  for (int i = 0; i < 4; ++i) {
    const float inv = 1.0f / lrun[i];
    float* row = Og + (size_t)(4 * ty + i) * kQS;
    *(float4*)(row + 4 * tx) =
        make_float4(o[i][0] * inv, o[i][1] * inv, o[i][2] * inv, o[i][3] * inv);
    *(float4*)(row + 64 + 4 * tx) =
        make_float4(o[i][4] * inv, o[i][5] * inv, o[i][6] * inv, o[i][7] * inv);
  }
}

// =====================================================================
// launch
// =====================================================================
extern "C" void kernel_launch(void* const* d_in, const int* in_sizes, int n_in,
                              void* d_out, int out_size) {
  const int*   positions = (const int*)d_in[0];
  const float* hidden    = (const float*)d_in[1];
  const float* wqkv      = (const float*)d_in[2];
  const float* wo        = (const float*)d_in[3];
  float*       out       = (float*)d_out;

  // Resolve device addresses of __device__ globals (host shadows are NOT
  // device pointers; on GB300/ATS passing them silently reads host zeros).
  void *p_qkv, *p_attn, *p_ah, *p_al, *p_b1h, *p_b1l, *p_b2h, *p_b2l;
  cudaGetSymbolAddress(&p_qkv,  g_qkv);
  cudaGetSymbolAddress(&p_attn, g_attn);
  cudaGetSymbolAddress(&p_ah,   g_ah);
  cudaGetSymbolAddress(&p_al,   g_al);
  cudaGetSymbolAddress(&p_b1h,  g_b1h);
  cudaGetSymbolAddress(&p_b1l,  g_b1l);
  cudaGetSymbolAddress(&p_b2h,  g_b2h);
  cudaGetSymbolAddress(&p_b2l,  g_b2l);

  float* qkv = (float*)p_qkv;
  float* attn = (float*)p_attn;
  __nv_bfloat16* ah = (__nv_bfloat16*)p_ah;
  __nv_bfloat16* al = (__nv_bfloat16*)p_al;
  __nv_bfloat16* b1h = (__nv_bfloat16*)p_b1h;
  __nv_bfloat16* b1l = (__nv_bfloat16*)p_b1l;
  __nv_bfloat16* b2h = (__nv_bfloat16*)p_b2h;
  __nv_bfloat16* b2l = (__nv_bfloat16*)p_b2l;

  constexpr int kAttnSmem = (3 * 64 * 128 + 64 * 64) * 4;
  cudaFuncSetAttribute(attn_kernel,
                       cudaFuncAttributeMaxDynamicSharedMemorySize, kAttnSmem);

  // QKV projection
  split_kernel<<<kT * kH / 4 / 256, 256>>>(hidden, ah, al, kT * kH / 4);
  transpose_split_kernel<<<dim3(kQKV / 32, kH / 32), dim3(32, 8)>>>(
      wqkv, b1h, b1l, kH, kQKV);
  gemm_mma_kernel<<<dim3(kQKV / 128, kT / 128), 256>>>(
      ah, al, b1h, b1l, qkv, kQKV);

  // RoPE + attention
  const int ropeTot = kT * (kNH + kNKV) * 64;
  rope_kernel<<<(ropeTot + 255) / 256, 256>>>(positions);
  attn_kernel<<<dim3(kNH, kT / 64), 256, kAttnSmem>>>();

  // Output projection
  split_kernel<<<kT * kQS / 4 / 256, 256>>>(attn, ah, al, kT * kQS / 4);
  transpose_split_kernel<<<dim3(kQS / 32, kH / 32), dim3(32, 8)>>>(
      wo, b2h, b2l, kH, kQS);
  gemm_mma_kernel<<<dim3(kQS / 128, kT / 128), 256>>>(
      ah, al, b2h, b2l, out, kQS);
}

// round 7
// speedup vs baseline: 2.1010x; 1.2647x over previous
#include <cuda_runtime.h>
#include <cuda_bf16.h>
#include <math.h>
#include <stdint.h>

// ----------------- problem constants -----------------
constexpr int kT    = 2048;
constexpr int kH    = 4096;
constexpr int kNH   = 32;
constexpr int kNKV  = 8;
constexpr int kHD   = 128;
constexpr int kQKV  = 6144;
constexpr int kQS   = 4096;
constexpr int kKOff = 4096;
constexpr int kVOff = 5120;

// ----------------- scratch (no allocations allowed) -----------------
__device__ float g_qkv[kT * kQKV];
__device__ float g_attn[kT * kQS];
__device__ __align__(16) __nv_bfloat16 g_ah[kT * kH];     // A hi (both gemms)
__device__ __align__(16) __nv_bfloat16 g_al[kT * kH];     // A lo
__device__ __align__(16) __nv_bfloat16 g_b1h[kQKV * kH];  // w_qkv^T hi [N,K]
__device__ __align__(16) __nv_bfloat16 g_b1l[kQKV * kH];
__device__ __align__(16) __nv_bfloat16 g_b2h[kQS * kH];   // w_o^T hi [N,K]
__device__ __align__(16) __nv_bfloat16 g_b2l[kQS * kH];

// ================= low-level helpers =================
__device__ __forceinline__ uint32_t smem_u32(const void* p) {
  uint32_t a;
  asm("{ .reg .u64 t; cvta.to.shared.u64 t, %1; cvt.u32.u64 %0, t; }"
      : "=r"(a) : "l"(p));
  return a;
}
__device__ __forceinline__ void ldsm4(uint32_t* r, uint32_t addr) {
  asm volatile("ldmatrix.sync.aligned.m8n8.x4.shared.b16 {%0,%1,%2,%3}, [%4];"
               : "=r"(r[0]), "=r"(r[1]), "=r"(r[2]), "=r"(r[3]) : "r"(addr));
}
__device__ __forceinline__ void mma_bf16(float* c, const uint32_t* a,
                                         uint32_t b0, uint32_t b1) {
  asm volatile(
      "mma.sync.aligned.m16n8k16.row.col.f32.bf16.bf16.f32 "
      "{%0,%1,%2,%3}, {%4,%5,%6,%7}, {%8,%9}, {%0,%1,%2,%3};"
      : "+f"(c[0]), "+f"(c[1]), "+f"(c[2]), "+f"(c[3])
      : "r"(a[0]), "r"(a[1]), "r"(a[2]), "r"(a[3]), "r"(b0), "r"(b1));
}

// =====================================================================
// Conversion kernels
// =====================================================================
__global__ void split_kernel(const float* __restrict__ X,
                             __nv_bfloat16* __restrict__ H,
                             __nv_bfloat16* __restrict__ L, int total4) {
  const int i = blockIdx.x * blockDim.x + threadIdx.x;
  if (i >= total4) return;
  const float4 v = ((const float4*)X)[i];
  __nv_bfloat16 hx = __float2bfloat16_rn(v.x);
  __nv_bfloat16 hy = __float2bfloat16_rn(v.y);
  __nv_bfloat16 hz = __float2bfloat16_rn(v.z);
  __nv_bfloat16 hw = __float2bfloat16_rn(v.w);
  __nv_bfloat162* Hp = (__nv_bfloat162*)H;
  Hp[2 * i]     = __nv_bfloat162(hx, hy);
  Hp[2 * i + 1] = __nv_bfloat162(hz, hw);
  __nv_bfloat162* Lp = (__nv_bfloat162*)L;
  Lp[2 * i] = __nv_bfloat162(__float2bfloat16_rn(v.x - __bfloat162float(hx)),
                             __float2bfloat16_rn(v.y - __bfloat162float(hy)));
  Lp[2 * i + 1] = __nv_bfloat162(__float2bfloat16_rn(v.z - __bfloat162float(hz)),
                                 __float2bfloat16_rn(v.w - __bfloat162float(hw)));
}

// W[K,N] fp32 -> Th/Tl[N,K] bf16 (transpose + split)
__global__ void transpose_split_kernel(const float* __restrict__ W,
                                       __nv_bfloat16* __restrict__ Th,
                                       __nv_bfloat16* __restrict__ Tl,
                                       int K, int N) {
  __shared__ float t[32][33];
  const int n0 = blockIdx.x * 32, k0 = blockIdx.y * 32;
  const int tx = threadIdx.x, ty = threadIdx.y;
#pragma unroll
  for (int j = 0; j < 4; ++j)
    t[ty + 8 * j][tx] = W[(size_t)(k0 + ty + 8 * j) * N + n0 + tx];
  __syncthreads();
#pragma unroll
  for (int j = 0; j < 4; ++j) {
    const int n = ty + 8 * j;
    const float v = t[tx][n];
    const __nv_bfloat16 h = __float2bfloat16_rn(v);
    const size_t o = (size_t)(n0 + n) * K + k0 + tx;
    Th[o] = h;
    Tl[o] = __float2bfloat16_rn(v - __bfloat162float(h));
  }
}

// =====================================================================
// bf16x3 GEMM on mma.sync (HMMA). C[M,NT] = A[M,4096] @ B^T[N,K].
// Block 128x128, BK=32, 8 warps (2x4), warp tile 64x32.
// Static smem, single stage, register-prefetch double buffering.
// Rows padded to 40 halves (80B) -> conflict-free ldmatrix, 16B aligned.
// =====================================================================
constexpr int kLds = 40;  // halves per smem row

__global__ __launch_bounds__(256)
void gemm_mma_kernel(const __nv_bfloat16* __restrict__ Ah,
                     const __nv_bfloat16* __restrict__ Al,
                     const __nv_bfloat16* __restrict__ Bh,
                     const __nv_bfloat16* __restrict__ Bl,
                     float* __restrict__ C, int NT) {
  constexpr int K = kH;        // 4096
  constexpr int BK = 32;
  constexpr int NST = K / BK;  // 128
  constexpr int TILE = 128 * kLds;  // halves per tile
  __shared__ __align__(16) __nv_bfloat16 smem[4 * TILE];  // 40960 B

  const int tid = threadIdx.x;
  const int wid = tid >> 5, lane = tid & 31;
  const int m0 = blockIdx.y << 7;
  const int n0 = blockIdx.x << 7;
  const int wm = (wid >> 2) << 6;  // 0/64
  const int wn = (wid & 3) << 5;   // 0/32/64/96

  const int lr = tid >> 2, ls = tid & 3;
  const uint32_t base = smem_u32(smem);

  float acc[4][4][4];
#pragma unroll
  for (int i = 0; i < 4; ++i)
#pragma unroll
    for (int j = 0; j < 4; ++j)
#pragma unroll
      for (int q = 0; q < 4; ++q) acc[i][j][q] = 0.f;

  const size_t aOff0 = (size_t)(m0 + lr) * K + ls * 8;
  const size_t aOff1 = aOff0 + (size_t)64 * K;
  const size_t bOff0 = (size_t)(n0 + lr) * K + ls * 8;
  const size_t bOff1 = bOff0 + (size_t)64 * K;

  // register staging for the next k-chunk
  uint4 rAh0, rAh1, rAl0, rAl1, rBh0, rBh1, rBl0, rBl1;
  rAh0 = *(const uint4*)(Ah + aOff0);
  rAh1 = *(const uint4*)(Ah + aOff1);
  rAl0 = *(const uint4*)(Al + aOff0);
  rAl1 = *(const uint4*)(Al + aOff1);
  rBh0 = *(const uint4*)(Bh + bOff0);
  rBh1 = *(const uint4*)(Bh + bOff1);
  rBl0 = *(const uint4*)(Bl + bOff0);
  rBl1 = *(const uint4*)(Bl + bOff1);

  const int s0 = lr * kLds + ls * 8;         // halves
  const int s1 = (lr + 64) * kLds + ls * 8;

#pragma unroll 1
  for (int kt = 0; kt < NST; ++kt) {
    __syncthreads();  // previous compute finished before overwrite
    *(uint4*)&smem[s0]            = rAh0;
    *(uint4*)&smem[s1]            = rAh1;
    *(uint4*)&smem[TILE + s0]     = rAl0;
    *(uint4*)&smem[TILE + s1]     = rAl1;
    *(uint4*)&smem[2 * TILE + s0] = rBh0;
    *(uint4*)&smem[2 * TILE + s1] = rBh1;
    *(uint4*)&smem[3 * TILE + s0] = rBl0;
    *(uint4*)&smem[3 * TILE + s1] = rBl1;
    __syncthreads();

    if (kt + 1 < NST) {  // prefetch next chunk (overlaps with compute below)
      const int kc = (kt + 1) * BK;
      rAh0 = *(const uint4*)(Ah + aOff0 + kc);
      rAh1 = *(const uint4*)(Ah + aOff1 + kc);
      rAl0 = *(const uint4*)(Al + aOff0 + kc);
      rAl1 = *(const uint4*)(Al + aOff1 + kc);
      rBh0 = *(const uint4*)(Bh + bOff0 + kc);
      rBh1 = *(const uint4*)(Bh + bOff1 + kc);
      rBl0 = *(const uint4*)(Bl + bOff0 + kc);
      rBl1 = *(const uint4*)(Bl + bOff1 + kc);
    }

#pragma unroll
    for (int kh = 0; kh < 2; ++kh) {
      const int slot = kh * 2 + (lane >> 4);   // 0..3
      const int arow = wm + (lane & 15);
      const int brow = wn + (lane & 15);

      uint32_t ah[4][4], al[4][4];
#pragma unroll
      for (int i = 0; i < 4; ++i) {
        const uint32_t ad = base + (uint32_t)(((arow + 16 * i) * kLds + slot * 8) * 2);
        ldsm4(ah[i], ad);
        ldsm4(al[i], ad + TILE * 2);
      }
      uint32_t bh[2][4], bl[2][4];
#pragma unroll
      for (int p = 0; p < 2; ++p) {
        const uint32_t bd = base + (uint32_t)(2 * TILE * 2) +
                            (uint32_t)(((brow + 16 * p) * kLds + slot * 8) * 2);
        ldsm4(bh[p], bd);
        ldsm4(bl[p], bd + TILE * 2);
      }
#pragma unroll
      for (int i = 0; i < 4; ++i)
#pragma unroll
        for (int j = 0; j < 4; ++j) {
          const int p = j >> 1, w = j & 1;
          mma_bf16(acc[i][j], ah[i], bh[p][w], bh[p][2 + w]);
          mma_bf16(acc[i][j], ah[i], bl[p][w], bl[p][2 + w]);
          mma_bf16(acc[i][j], al[i], bh[p][w], bh[p][2 + w]);
        }
    }
  }

  // ---- epilogue ----
  const int g = lane >> 2, t4 = lane & 3;
#pragma unroll
  for (int i = 0; i < 4; ++i) {
    const int r0 = m0 + wm + 16 * i + g;
#pragma unroll
    for (int j = 0; j < 4; ++j) {
      const int col = n0 + wn + 8 * j + 2 * t4;
      *(float2*)(C + (size_t)r0 * NT + col) =
          make_float2(acc[i][j][0], acc[i][j][1]);
      *(float2*)(C + (size_t)(r0 + 8) * NT + col) =
          make_float2(acc[i][j][2], acc[i][j][3]);
    }
  }
}

// =====================================================================
// RoPE in place. fp32 inv_freq via exp2f (matches reference fp32 pow to ~2ulp).
// =====================================================================
__global__ void rope_kernel(const int* __restrict__ pos) {
  const int idx = blockIdx.x * blockDim.x + threadIdx.x;
  const int totq = kT * kNH * 64;
  const int tot = totq + kT * kNKV * 64;
  if (idx >= tot) return;

  float* base;
  int t, i;
  if (idx < totq) {
    t = idx / (kNH * 64);
    const int r = idx - t * (kNH * 64);
    i = r & 63;
    base = g_qkv + (size_t)t * kQKV + (r >> 6) * kHD;
  } else {
    const int j = idx - totq;
    t = j / (kNKV * 64);
    const int r = j - t * (kNKV * 64);
    i = r & 63;
    base = g_qkv + (size_t)t * kQKV + kKOff + (r >> 6) * kHD;
  }
  // inv_freq = 500000^(-i/64) = exp2(-i * log2(500000)/64), fp32
  constexpr float kNegLog2Theta64 = -0.29580667120644826f;  // -log2(5e5)/64
  const float inv = exp2f((float)i * kNegLog2Theta64);
  const float f = (float)pos[t] * inv;
  float sn, cs;
  sincosf(f, &sn, &cs);
  const float x1 = base[i], x2 = base[i + 64];
  base[i] = x1 * cs - x2 * sn;
  base[i + 64] = x2 * cs + x1 * sn;
}

// =====================================================================
// Flash attention fp32 (unchanged, proven)
// =====================================================================
__device__ __forceinline__ int swz(int r, int c4) {
  return c4 ^ ((r >> 2) & 7) ^ ((r & 3) << 3);
}

__global__ __launch_bounds__(256)
void attn_kernel() {
  extern __shared__ float sm[];
  float* sQ = sm;
  float* sK = sm + 8192;
  float* sV = sm + 16384;
  float* sP = sm + 24576;

  const int h = blockIdx.x;
  const int qb = (int)gridDim.y - 1 - (int)blockIdx.y;
  const int kvh = h >> 2;
  const int tid = threadIdx.x;
  const int tx = tid & 15, ty = tid >> 4;
  const int q0 = qb << 6;

  const float scale = 0.08838834764831845f;

  {
    const float* Qg = g_qkv + (size_t)q0 * kQKV + h * kHD;
#pragma unroll
    for (int it = 0; it < 8; ++it) {
      const int idx = tid + (it << 8);
      const int r = idx >> 5, c4 = idx & 31;
      float4 v = *(const float4*)(Qg + (size_t)r * kQKV + (c4 << 2));
      v.x *= scale; v.y *= scale; v.z *= scale; v.w *= scale;
      *(float4*)(sQ + (r << 7) + (swz(r, c4) << 2)) = v;
    }
  }

  float o[4][8];
  float mrun[4], lrun[4];
#pragma unroll
  for (int i = 0; i < 4; ++i) {
    mrun[i] = -1e30f; lrun[i] = 0.f;
#pragma unroll
    for (int c = 0; c < 8; ++c) o[i][c] = 0.f;
  }

  int qswz[4], kswz[4];
#pragma unroll
  for (int i = 0; i < 4; ++i) {
    const int rq = 4 * ty + i;
    qswz[i] = ((rq >> 2) & 7) ^ ((rq & 3) << 3);
    const int rk = 4 * tx + i;
    kswz[i] = ((rk >> 2) & 7) ^ ((rk & 3) << 3);
  }
  __syncthreads();

  const int nblk = qb + 1;
  for (int b = 0; b < nblk; ++b) {
    const int s0 = b << 6;
    const float* Kg = g_qkv + (size_t)s0 * kQKV + kKOff + kvh * kHD;
    const float* Vg = g_qkv + (size_t)s0 * kQKV + kVOff + kvh * kHD;
#pragma unroll
    for (int it = 0; it < 8; ++it) {
      const int idx = tid + (it << 8);
      const int r = idx >> 5, c4 = idx & 31;
      const int so = (r << 7) + (swz(r, c4) << 2);
      *(float4*)(sK + so) = *(const float4*)(Kg + (size_t)r * kQKV + (c4 << 2));
      *(float4*)(sV + so) = *(const float4*)(Vg + (size_t)r * kQKV + (c4 << 2));
    }
    __syncthreads();

    float s[4][4];
#pragma unroll
    for (int i = 0; i < 4; ++i)
#pragma unroll
      for (int j = 0; j < 4; ++j) s[i][j] = 0.f;

#pragma unroll 8
    for (int d4 = 0; d4 < 32; ++d4) {
      float4 qv[4], kv[4];
#pragma unroll
      for (int i = 0; i < 4; ++i)
        qv[i] = *(const float4*)(sQ + ((4 * ty + i) << 7) + ((d4 ^ qswz[i]) << 2));
#pragma unroll
      for (int j = 0; j < 4; ++j)
        kv[j] = *(const float4*)(sK + ((4 * tx + j) << 7) + ((d4 ^ kswz[j]) << 2));
#pragma unroll
      for (int i = 0; i < 4; ++i)
#pragma unroll
        for (int j = 0; j < 4; ++j)
          s[i][j] += qv[i].x * kv[j].x + qv[i].y * kv[j].y +
                     qv[i].z * kv[j].z + qv[i].w * kv[j].w;
    }

    if (s0 == q0) {
#pragma unroll
      for (int i = 0; i < 4; ++i)
#pragma unroll
        for (int j = 0; j < 4; ++j)
          if (4 * tx + j > 4 * ty + i) s[i][j] = -1e30f;
    }

#pragma unroll
    for (int i = 0; i < 4; ++i) {
      float mx = fmaxf(fmaxf(s[i][0], s[i][1]), fmaxf(s[i][2], s[i][3]));
#pragma unroll
      for (int w = 1; w < 16; w <<= 1)
        mx = fmaxf(mx, __shfl_xor_sync(0xffffffffu, mx, w));
      const float mnew = fmaxf(mrun[i], mx);
      const float fac = __expf(mrun[i] - mnew);
      float rs = 0.f;
#pragma unroll
      for (int j = 0; j < 4; ++j) {
        s[i][j] = __expf(s[i][j] - mnew);
        rs += s[i][j];
      }
#pragma unroll
      for (int w = 1; w < 16; w <<= 1)
        rs += __shfl_xor_sync(0xffffffffu, rs, w);
      lrun[i] = lrun[i] * fac + rs;
      mrun[i] = mnew;
#pragma unroll
      for (int c = 0; c < 8; ++c) o[i][c] *= fac;
    }

#pragma unroll
    for (int i = 0; i < 4; ++i)
      *(float4*)(sP + ((4 * ty + i) << 6) + 4 * tx) =
          make_float4(s[i][0], s[i][1], s[i][2], s[i][3]);
    __syncthreads();

#pragma unroll 4
    for (int s4 = 0; s4 < 16; ++s4) {
      float4 p4[4];
#pragma unroll
      for (int i = 0; i < 4; ++i)
        p4[i] = *(const float4*)(sP + ((4 * ty + i) << 6) + (s4 << 2));
#pragma unroll
      for (int u = 0; u < 4; ++u) {
        const int srow = (s4 << 2) + u;
        const int sw = ((srow >> 2) & 7) ^ ((srow & 3) << 3);
        const float4 v0 = *(const float4*)(sV + (srow << 7) + ((tx ^ sw) << 2));
        const float4 v1 = *(const float4*)(sV + (srow << 7) + (((16 + tx) ^ sw) << 2));
#pragma unroll
        for (int i = 0; i < 4; ++i) {
          const float pv = (&p4[i].x)[u];
          o[i][0] += pv * v0.x; o[i][1] += pv * v0.y;
          o[i][2] += pv * v0.z; o[i][3] += pv * v0.w;
          o[i][4] += pv * v1.x; o[i][5] += pv * v1.y;
          o[i][6] += pv * v1.z; o[i][7] += pv * v1.w;
        }
      }
    }
    __syncthreads();
  }

  float* Og = g_attn + (size_t)q0 * kQS + h * kHD;
#pragma unroll
  for (int i = 0; i < 4; ++i) {
    const float inv = 1.0f / lrun[i];
    float* row = Og + (size_t)(4 * ty + i) * kQS;
    *(float4*)(row + 4 * tx) =
        make_float4(o[i][0] * inv, o[i][1] * inv, o[i][2] * inv, o[i][3] * inv);
    *(float4*)(row + 64 + 4 * tx) =
        make_float4(o[i][4] * inv, o[i][5] * inv, o[i][6] * inv, o[i][7] * inv);
  }
}

// =====================================================================
// launch
// =====================================================================
extern "C" void kernel_launch(void* const* d_in, const int* in_sizes, int n_in,
                              void* d_out, int out_size) {
  const int*   positions = (const int*)d_in[0];
  const float* hidden    = (const float*)d_in[1];
  const float* wqkv      = (const float*)d_in[2];
  const float* wo        = (const float*)d_in[3];
  float*       out       = (float*)d_out;

  // Resolve device addresses of __device__ globals (host shadows are NOT
  // device pointers; on GB300/ATS passing them silently reads host zeros).
  void *p_qkv, *p_attn, *p_ah, *p_al, *p_b1h, *p_b1l, *p_b2h, *p_b2l;
  cudaGetSymbolAddress(&p_qkv,  g_qkv);
  cudaGetSymbolAddress(&p_attn, g_attn);
  cudaGetSymbolAddress(&p_ah,   g_ah);
  cudaGetSymbolAddress(&p_al,   g_al);
  cudaGetSymbolAddress(&p_b1h,  g_b1h);
  cudaGetSymbolAddress(&p_b1l,  g_b1l);
  cudaGetSymbolAddress(&p_b2h,  g_b2h);
  cudaGetSymbolAddress(&p_b2l,  g_b2l);

  float* qkv = (float*)p_qkv;
  float* attn = (float*)p_attn;
  __nv_bfloat16* ah = (__nv_bfloat16*)p_ah;
  __nv_bfloat16* al = (__nv_bfloat16*)p_al;
  __nv_bfloat16* b1h = (__nv_bfloat16*)p_b1h;
  __nv_bfloat16* b1l = (__nv_bfloat16*)p_b1l;
  __nv_bfloat16* b2h = (__nv_bfloat16*)p_b2h;
  __nv_bfloat16* b2l = (__nv_bfloat16*)p_b2l;

  constexpr int kAttnSmem = (3 * 64 * 128 + 64 * 64) * 4;
  cudaFuncSetAttribute(attn_kernel,
                       cudaFuncAttributeMaxDynamicSharedMemorySize, kAttnSmem);

  // QKV projection
  split_kernel<<<kT * kH / 4 / 256, 256>>>(hidden, ah, al, kT * kH / 4);
  transpose_split_kernel<<<dim3(kQKV / 32, kH / 32), dim3(32, 8)>>>(
      wqkv, b1h, b1l, kH, kQKV);
  gemm_mma_kernel<<<dim3(kQKV / 128, kT / 128), 256>>>(
      ah, al, b1h, b1l, qkv, kQKV);

  // RoPE + attention
  const int ropeTot = kT * (kNH + kNKV) * 64;
  rope_kernel<<<(ropeTot + 255) / 256, 256>>>(positions);
  attn_kernel<<<dim3(kNH, kT / 64), 256, kAttnSmem>>>();

  // Output projection
  split_kernel<<<kT * kQS / 4 / 256, 256>>>(attn, ah, al, kT * kQS / 4);
  transpose_split_kernel<<<dim3(kQS / 32, kH / 32), dim3(32, 8)>>>(
      wo, b2h, b2l, kH, kQS);
  gemm_mma_kernel<<<dim3(kQS / 128, kT / 128), 256>>>(
      ah, al, b2h, b2l, out, kQS);
}

// round 8
// speedup vs baseline: 2.7323x; 1.3005x over previous
#include <cuda_runtime.h>
#include <cuda_bf16.h>
#include <math.h>
#include <stdint.h>

// ----------------- problem constants -----------------
constexpr int kT    = 2048;
constexpr int kH    = 4096;
constexpr int kNH   = 32;
constexpr int kNKV  = 8;
constexpr int kHD   = 128;
constexpr int kQKV  = 6144;
constexpr int kQS   = 4096;
constexpr int kKOff = 4096;
constexpr int kVOff = 5120;

// ----------------- scratch (no allocations allowed) -----------------
__device__ float g_qkv[kT * kQKV];
__device__ __align__(16) __nv_bfloat16 g_ah[kT * kH];     // GEMM A hi
__device__ __align__(16) __nv_bfloat16 g_al[kT * kH];     // GEMM A lo
__device__ __align__(16) __nv_bfloat16 g_b1h[kQKV * kH];  // w_qkv^T hi [N,K]
__device__ __align__(16) __nv_bfloat16 g_b1l[kQKV * kH];
__device__ __align__(16) __nv_bfloat16 g_b2h[kQS * kH];   // w_o^T hi [N,K]
__device__ __align__(16) __nv_bfloat16 g_b2l[kQS * kH];
__device__ __align__(16) __nv_bfloat16 g_qh[kNH * kT * kHD];   // q scaled hi [h][t][d]
__device__ __align__(16) __nv_bfloat16 g_ql[kNH * kT * kHD];
__device__ __align__(16) __nv_bfloat16 g_kh[kNKV * kT * kHD];  // k hi [kv][t][d]
__device__ __align__(16) __nv_bfloat16 g_kl[kNKV * kT * kHD];
__device__ __align__(16) __nv_bfloat16 g_vh[kNKV * kT * kHD];
__device__ __align__(16) __nv_bfloat16 g_vl[kNKV * kT * kHD];

// ================= low-level helpers =================
__device__ __forceinline__ uint32_t smem_u32(const void* p) {
  uint32_t a;
  asm("{ .reg .u64 t; cvta.to.shared.u64 t, %1; cvt.u32.u64 %0, t; }"
      : "=r"(a) : "l"(p));
  return a;
}
__device__ __forceinline__ void ldsm4(uint32_t* r, uint32_t addr) {
  asm volatile("ldmatrix.sync.aligned.m8n8.x4.shared.b16 {%0,%1,%2,%3}, [%4];"
               : "=r"(r[0]), "=r"(r[1]), "=r"(r[2]), "=r"(r[3]) : "r"(addr));
}
__device__ __forceinline__ void ldsm4t(uint32_t* r, uint32_t addr) {
  asm volatile("ldmatrix.sync.aligned.m8n8.x4.trans.shared.b16 {%0,%1,%2,%3}, [%4];"
               : "=r"(r[0]), "=r"(r[1]), "=r"(r[2]), "=r"(r[3]) : "r"(addr));
}
__device__ __forceinline__ void mma_bf16(float* c, const uint32_t* a,
                                         uint32_t b0, uint32_t b1) {
  asm volatile(
      "mma.sync.aligned.m16n8k16.row.col.f32.bf16.bf16.f32 "
      "{%0,%1,%2,%3}, {%4,%5,%6,%7}, {%8,%9}, {%0,%1,%2,%3};"
      : "+f"(c[0]), "+f"(c[1]), "+f"(c[2]), "+f"(c[3])
      : "r"(a[0]), "r"(a[1]), "r"(a[2]), "r"(a[3]), "r"(b0), "r"(b1));
}
// split (x,y) into bf16 hi pair (returned) and lo pair (out param)
__device__ __forceinline__ uint32_t packsplit(float x, float y, uint32_t& lo) {
  __nv_bfloat16 hx = __float2bfloat16_rn(x);
  __nv_bfloat16 hy = __float2bfloat16_rn(y);
  __nv_bfloat162 hp(hx, hy);
  __nv_bfloat162 lp(__float2bfloat16_rn(x - __bfloat162float(hx)),
                    __float2bfloat16_rn(y - __bfloat162float(hy)));
  lo = *(uint32_t*)&lp;
  return *(uint32_t*)&hp;
}

// =====================================================================
// Conversion kernels
// =====================================================================
__global__ void split_kernel(const float* __restrict__ X,
                             __nv_bfloat16* __restrict__ H,
                             __nv_bfloat16* __restrict__ L, int total4) {
  const int i = blockIdx.x * blockDim.x + threadIdx.x;
  if (i >= total4) return;
  const float4 v = ((const float4*)X)[i];
  uint32_t l0, l1;
  const uint32_t h0 = packsplit(v.x, v.y, l0);
  const uint32_t h1 = packsplit(v.z, v.w, l1);
  ((uint2*)H)[i] = make_uint2(h0, h1);
  ((uint2*)L)[i] = make_uint2(l0, l1);
}

// W[K,N] fp32 -> Th/Tl[N,K] bf16 (transpose + split)
__global__ void transpose_split_kernel(const float* __restrict__ W,
                                       __nv_bfloat16* __restrict__ Th,
                                       __nv_bfloat16* __restrict__ Tl,
                                       int K, int N) {
  __shared__ float t[32][33];
  const int n0 = blockIdx.x * 32, k0 = blockIdx.y * 32;
  const int tx = threadIdx.x, ty = threadIdx.y;
#pragma unroll
  for (int j = 0; j < 4; ++j)
    t[ty + 8 * j][tx] = W[(size_t)(k0 + ty + 8 * j) * N + n0 + tx];
  __syncthreads();
#pragma unroll
  for (int j = 0; j < 4; ++j) {
    const int n = ty + 8 * j;
    const float v = t[tx][n];
    const __nv_bfloat16 h = __float2bfloat16_rn(v);
    const size_t o = (size_t)(n0 + n) * K + k0 + tx;
    Th[o] = h;
    Tl[o] = __float2bfloat16_rn(v - __bfloat162float(h));
  }
}

// q region of g_qkv -> scaled hi/lo, layout [h][t][d]
__global__ void qsplit_kernel(const float* __restrict__ qkv,
                              __nv_bfloat16* __restrict__ qh,
                              __nv_bfloat16* __restrict__ ql) {
  const int i = blockIdx.x * blockDim.x + threadIdx.x;
  if (i >= kT * kQS / 4) return;
  const int e = i * 4;
  const int t = e >> 12;
  const int rem = e & 4095;
  const int hh = rem >> 7, d = rem & 127;
  const float4 v = *(const float4*)(qkv + (size_t)t * kQKV + rem);
  constexpr float sc = 0.08838834764831845f;  // 1/sqrt(128)
  uint32_t l0, l1;
  const uint32_t h0 = packsplit(v.x * sc, v.y * sc, l0);
  const uint32_t h1 = packsplit(v.z * sc, v.w * sc, l1);
  const size_t o = ((size_t)hh * kT + t) * kHD + d;
  *(uint2*)(qh + o) = make_uint2(h0, h1);
  *(uint2*)(ql + o) = make_uint2(l0, l1);
}

// k and v regions of g_qkv -> hi/lo, layout [kv][t][d]
__global__ void kvsplit_kernel(const float* __restrict__ qkv,
                               __nv_bfloat16* __restrict__ kh,
                               __nv_bfloat16* __restrict__ kl,
                               __nv_bfloat16* __restrict__ vh,
                               __nv_bfloat16* __restrict__ vl) {
  const int i = blockIdx.x * blockDim.x + threadIdx.x;
  if (i >= kT * 1024 / 4) return;
  const int e = i * 4;
  const int t = e >> 10;
  const int rem = e & 1023;
  const int kv = rem >> 7, d = rem & 127;
  const size_t o = ((size_t)kv * kT + t) * kHD + d;
  const float4 kf = *(const float4*)(qkv + (size_t)t * kQKV + kKOff + rem);
  const float4 vf = *(const float4*)(qkv + (size_t)t * kQKV + kVOff + rem);
  uint32_t l0, l1;
  uint32_t h0 = packsplit(kf.x, kf.y, l0);
  uint32_t h1 = packsplit(kf.z, kf.w, l1);
  *(uint2*)(kh + o) = make_uint2(h0, h1);
  *(uint2*)(kl + o) = make_uint2(l0, l1);
  h0 = packsplit(vf.x, vf.y, l0);
  h1 = packsplit(vf.z, vf.w, l1);
  *(uint2*)(vh + o) = make_uint2(h0, h1);
  *(uint2*)(vl + o) = make_uint2(l0, l1);
}

// =====================================================================
// bf16x3 GEMM on mma.sync (proven). C[M,NT] = A[M,4096] @ B^T[N,K].
// =====================================================================
constexpr int kLds = 40;

__global__ __launch_bounds__(256)
void gemm_mma_kernel(const __nv_bfloat16* __restrict__ Ah,
                     const __nv_bfloat16* __restrict__ Al,
                     const __nv_bfloat16* __restrict__ Bh,
                     const __nv_bfloat16* __restrict__ Bl,
                     float* __restrict__ C, int NT) {
  constexpr int K = kH;
  constexpr int BK = 32;
  constexpr int NST = K / BK;
  constexpr int TILE = 128 * kLds;
  __shared__ __align__(16) __nv_bfloat16 smem[4 * TILE];

  const int tid = threadIdx.x;
  const int wid = tid >> 5, lane = tid & 31;
  const int m0 = blockIdx.y << 7;
  const int n0 = blockIdx.x << 7;
  const int wm = (wid >> 2) << 6;
  const int wn = (wid & 3) << 5;

  const int lr = tid >> 2, ls = tid & 3;
  const uint32_t base = smem_u32(smem);

  float acc[4][4][4];
#pragma unroll
  for (int i = 0; i < 4; ++i)
#pragma unroll
    for (int j = 0; j < 4; ++j)
#pragma unroll
      for (int q = 0; q < 4; ++q) acc[i][j][q] = 0.f;

  const size_t aOff0 = (size_t)(m0 + lr) * K + ls * 8;
  const size_t aOff1 = aOff0 + (size_t)64 * K;
  const size_t bOff0 = (size_t)(n0 + lr) * K + ls * 8;
  const size_t bOff1 = bOff0 + (size_t)64 * K;

  uint4 rAh0, rAh1, rAl0, rAl1, rBh0, rBh1, rBl0, rBl1;
  rAh0 = *(const uint4*)(Ah + aOff0);
  rAh1 = *(const uint4*)(Ah + aOff1);
  rAl0 = *(const uint4*)(Al + aOff0);
  rAl1 = *(const uint4*)(Al + aOff1);
  rBh0 = *(const uint4*)(Bh + bOff0);
  rBh1 = *(const uint4*)(Bh + bOff1);
  rBl0 = *(const uint4*)(Bl + bOff0);
  rBl1 = *(const uint4*)(Bl + bOff1);

  const int s0 = lr * kLds + ls * 8;
  const int s1 = (lr + 64) * kLds + ls * 8;

#pragma unroll 1
  for (int kt = 0; kt < NST; ++kt) {
    __syncthreads();
    *(uint4*)&smem[s0]            = rAh0;
    *(uint4*)&smem[s1]            = rAh1;
    *(uint4*)&smem[TILE + s0]     = rAl0;
    *(uint4*)&smem[TILE + s1]     = rAl1;
    *(uint4*)&smem[2 * TILE + s0] = rBh0;
    *(uint4*)&smem[2 * TILE + s1] = rBh1;
    *(uint4*)&smem[3 * TILE + s0] = rBl0;
    *(uint4*)&smem[3 * TILE + s1] = rBl1;
    __syncthreads();

    if (kt + 1 < NST) {
      const int kc = (kt + 1) * BK;
      rAh0 = *(const uint4*)(Ah + aOff0 + kc);
      rAh1 = *(const uint4*)(Ah + aOff1 + kc);
      rAl0 = *(const uint4*)(Al + aOff0 + kc);
      rAl1 = *(const uint4*)(Al + aOff1 + kc);
      rBh0 = *(const uint4*)(Bh + bOff0 + kc);
      rBh1 = *(const uint4*)(Bh + bOff1 + kc);
      rBl0 = *(const uint4*)(Bl + bOff0 + kc);
      rBl1 = *(const uint4*)(Bl + bOff1 + kc);
    }

#pragma unroll
    for (int kh = 0; kh < 2; ++kh) {
      const int slot = kh * 2 + (lane >> 4);
      const int arow = wm + (lane & 15);
      const int brow = wn + (lane & 15);

      uint32_t ah[4][4], al[4][4];
#pragma unroll
      for (int i = 0; i < 4; ++i) {
        const uint32_t ad = base + (uint32_t)(((arow + 16 * i) * kLds + slot * 8) * 2);
        ldsm4(ah[i], ad);
        ldsm4(al[i], ad + TILE * 2);
      }
      uint32_t bh[2][4], bl[2][4];
#pragma unroll
      for (int p = 0; p < 2; ++p) {
        const uint32_t bd = base + (uint32_t)(2 * TILE * 2) +
                            (uint32_t)(((brow + 16 * p) * kLds + slot * 8) * 2);
        ldsm4(bh[p], bd);
        ldsm4(bl[p], bd + TILE * 2);
      }
#pragma unroll
      for (int i = 0; i < 4; ++i)
#pragma unroll
        for (int j = 0; j < 4; ++j) {
          const int p = j >> 1, w = j & 1;
          mma_bf16(acc[i][j], ah[i], bh[p][w], bh[p][2 + w]);
          mma_bf16(acc[i][j], ah[i], bl[p][w], bl[p][2 + w]);
          mma_bf16(acc[i][j], al[i], bh[p][w], bh[p][2 + w]);
        }
    }
  }

  const int g = lane >> 2, t4 = lane & 3;
#pragma unroll
  for (int i = 0; i < 4; ++i) {
    const int r0 = m0 + wm + 16 * i + g;
#pragma unroll
    for (int j = 0; j < 4; ++j) {
      const int col = n0 + wn + 8 * j + 2 * t4;
      *(float2*)(C + (size_t)r0 * NT + col) =
          make_float2(acc[i][j][0], acc[i][j][1]);
      *(float2*)(C + (size_t)(r0 + 8) * NT + col) =
          make_float2(acc[i][j][2], acc[i][j][3]);
    }
  }
}

// =====================================================================
// RoPE in place (fp32 exp2f inv_freq)
// =====================================================================
__global__ void rope_kernel(const int* __restrict__ pos) {
  const int idx = blockIdx.x * blockDim.x + threadIdx.x;
  const int totq = kT * kNH * 64;
  const int tot = totq + kT * kNKV * 64;
  if (idx >= tot) return;

  float* base;
  int t, i;
  if (idx < totq) {
    t = idx / (kNH * 64);
    const int r = idx - t * (kNH * 64);
    i = r & 63;
    base = g_qkv + (size_t)t * kQKV + (r >> 6) * kHD;
  } else {
    const int j = idx - totq;
    t = j / (kNKV * 64);
    const int r = j - t * (kNKV * 64);
    i = r & 63;
    base = g_qkv + (size_t)t * kQKV + kKOff + (r >> 6) * kHD;
  }
  constexpr float kNegLog2Theta64 = -0.29580667120644826f;
  const float inv = exp2f((float)i * kNegLog2Theta64);
  const float f = (float)pos[t] * inv;
  float sn, cs;
  sincosf(f, &sn, &cs);
  const float x1 = base[i], x2 = base[i + 64];
  base[i] = x1 * cs - x2 * sn;
  base[i + 64] = x2 * cs + x1 * sn;
}

// =====================================================================
// Flash attention on mma.sync, bf16x3. CTA = (head, 64 q-rows), 4 warps.
// smem tiles 64x128 bf16, rows padded to 136 halves (conflict-free ldsm).
// Tiles: [0]Qh [1]Ql [2]Kh [3]Kl [4]Vh [5]Vl.
// Output written as bf16 hi/lo directly into GEMM2's A buffers.
// =====================================================================
constexpr int kAPad  = 136;            // halves per row
constexpr int kATile = 64 * kAPad;     // halves per tile
constexpr uint32_t kTileB = kATile * 2;  // bytes per tile

__global__ __launch_bounds__(128)
void attn_mma_kernel(const __nv_bfloat16* __restrict__ qh,
                     const __nv_bfloat16* __restrict__ ql,
                     const __nv_bfloat16* __restrict__ kh,
                     const __nv_bfloat16* __restrict__ kl,
                     const __nv_bfloat16* __restrict__ vh,
                     const __nv_bfloat16* __restrict__ vl,
                     __nv_bfloat16* __restrict__ oh,
                     __nv_bfloat16* __restrict__ ol) {
  extern __shared__ __nv_bfloat16 sma[];
  const int h = blockIdx.x;
  const int qb = (int)gridDim.y - 1 - (int)blockIdx.y;  // heavy first
  const int kvi = h >> 2;
  const int tid = threadIdx.x;
  const int wid = tid >> 5, lane = tid & 31;
  const int q0 = qb << 6;
  const uint32_t base = smem_u32(sma);
  const int g = lane >> 2, t4 = lane & 3;

  // ---- load Q tiles once ----
  {
    const __nv_bfloat16* Qh = qh + ((size_t)h * kT + q0) * kHD;
    const __nv_bfloat16* Ql = ql + ((size_t)h * kT + q0) * kHD;
#pragma unroll
    for (int j = 0; j < 8; ++j) {
      const int idx = tid + (j << 7);
      const int r = idx >> 4, s = idx & 15;
      const int so = r * kAPad + s * 8;
      *(uint4*)(sma + so)          = *(const uint4*)(Qh + r * 128 + s * 8);
      *(uint4*)(sma + kATile + so) = *(const uint4*)(Ql + r * 128 + s * 8);
    }
  }

  float o[16][4];
#pragma unroll
  for (int t = 0; t < 16; ++t)
#pragma unroll
    for (int q = 0; q < 4; ++q) o[t][q] = 0.f;
  float mrun0 = -1e30f, mrun1 = -1e30f, lrun0 = 0.f, lrun1 = 0.f;

  // ldsm base addresses (bytes); k-chunk kc adds kc*32 bytes
  const uint32_t aAddr =
      base + 2u * (uint32_t)(((wid << 4) + (lane & 15)) * kAPad + ((lane >> 4) << 3));
  const uint32_t kAddr =
      base + 2u * kATile * 2u +
      2u * (uint32_t)((lane & 15) * kAPad + ((lane >> 4) << 3));
  const uint32_t vAddr =
      base + 4u * kTileB +
      2u * (uint32_t)((lane & 15) * kAPad + ((lane >> 4) << 3));

#pragma unroll 1
  for (int kb = 0; kb <= qb; ++kb) {
    __syncthreads();
    // ---- load K/V tiles ----
    const size_t kvoff = ((size_t)kvi * kT + ((size_t)kb << 6)) * kHD;
#pragma unroll
    for (int j = 0; j < 8; ++j) {
      const int idx = tid + (j << 7);
      const int r = idx >> 4, s = idx & 15;
      const int so = r * kAPad + s * 8;
      const size_t go = kvoff + r * 128 + s * 8;
      *(uint4*)(sma + 2 * kATile + so) = *(const uint4*)(kh + go);
      *(uint4*)(sma + 3 * kATile + so) = *(const uint4*)(kl + go);
      *(uint4*)(sma + 4 * kATile + so) = *(const uint4*)(vh + go);
      *(uint4*)(sma + 5 * kATile + so) = *(const uint4*)(vl + go);
    }
    __syncthreads();

    // ---- S = Q K^T (bf16x3) ----
    float sacc[8][4];
#pragma unroll
    for (int j = 0; j < 8; ++j)
#pragma unroll
      for (int q = 0; q < 4; ++q) sacc[j][q] = 0.f;

#pragma unroll
    for (int kc = 0; kc < 8; ++kc) {
      uint32_t aq[4], aql_[4];
      const uint32_t ad = aAddr + kc * 32;
      ldsm4(aq, ad);
      ldsm4(aql_, ad + kTileB);
#pragma unroll
      for (int p = 0; p < 4; ++p) {
        uint32_t bk[4], bkl_[4];
        const uint32_t bd = kAddr + (uint32_t)(p * 16 * kAPad * 2) + kc * 32;
        ldsm4(bk, bd);
        ldsm4(bkl_, bd + kTileB);
#pragma unroll
        for (int w2 = 0; w2 < 2; ++w2) {
          const int j = p * 2 + w2;
          mma_bf16(sacc[j], aq, bk[w2], bk[2 + w2]);
          mma_bf16(sacc[j], aq, bkl_[w2], bkl_[2 + w2]);
          mma_bf16(sacc[j], aql_, bk[w2], bk[2 + w2]);
        }
      }
    }

    // ---- causal mask (diagonal block only) ----
    if (kb == qb) {
      const int r0 = (wid << 4) + g;
#pragma unroll
      for (int j = 0; j < 8; ++j) {
        const int c = (j << 3) + (t4 << 1);
        if (c > r0)         sacc[j][0] = -1e30f;
        if (c + 1 > r0)     sacc[j][1] = -1e30f;
        if (c > r0 + 8)     sacc[j][2] = -1e30f;
        if (c + 1 > r0 + 8) sacc[j][3] = -1e30f;
      }
    }

    // ---- online softmax (rows g, g+8) ----
    float mx0 = -1e30f, mx1 = -1e30f;
#pragma unroll
    for (int j = 0; j < 8; ++j) {
      mx0 = fmaxf(mx0, fmaxf(sacc[j][0], sacc[j][1]));
      mx1 = fmaxf(mx1, fmaxf(sacc[j][2], sacc[j][3]));
    }
    mx0 = fmaxf(mx0, __shfl_xor_sync(0xffffffffu, mx0, 1));
    mx0 = fmaxf(mx0, __shfl_xor_sync(0xffffffffu, mx0, 2));
    mx1 = fmaxf(mx1, __shfl_xor_sync(0xffffffffu, mx1, 1));
    mx1 = fmaxf(mx1, __shfl_xor_sync(0xffffffffu, mx1, 2));
    const float mn0 = fmaxf(mrun0, mx0), mn1 = fmaxf(mrun1, mx1);
    const float f0 = __expf(mrun0 - mn0), f1 = __expf(mrun1 - mn1);
    float rs0 = 0.f, rs1 = 0.f;
#pragma unroll
    for (int j = 0; j < 8; ++j) {
      sacc[j][0] = __expf(sacc[j][0] - mn0);
      sacc[j][1] = __expf(sacc[j][1] - mn0);
      sacc[j][2] = __expf(sacc[j][2] - mn1);
      sacc[j][3] = __expf(sacc[j][3] - mn1);
      rs0 += sacc[j][0] + sacc[j][1];
      rs1 += sacc[j][2] + sacc[j][3];
    }
    rs0 += __shfl_xor_sync(0xffffffffu, rs0, 1);
    rs0 += __shfl_xor_sync(0xffffffffu, rs0, 2);
    rs1 += __shfl_xor_sync(0xffffffffu, rs1, 1);
    rs1 += __shfl_xor_sync(0xffffffffu, rs1, 2);
    lrun0 = lrun0 * f0 + rs0;
    lrun1 = lrun1 * f1 + rs1;
    mrun0 = mn0;
    mrun1 = mn1;
#pragma unroll
    for (int t = 0; t < 16; ++t) {
      o[t][0] *= f0; o[t][1] *= f0; o[t][2] *= f1; o[t][3] *= f1;
    }

    // ---- P fragments (C layout == A layout), hi/lo split ----
    uint32_t pha[4][4], pla[4][4];
#pragma unroll
    for (int jj = 0; jj < 4; ++jj) {
      pha[jj][0] = packsplit(sacc[2 * jj][0], sacc[2 * jj][1], pla[jj][0]);
      pha[jj][1] = packsplit(sacc[2 * jj][2], sacc[2 * jj][3], pla[jj][1]);
      pha[jj][2] = packsplit(sacc[2 * jj + 1][0], sacc[2 * jj + 1][1], pla[jj][2]);
      pha[jj][3] = packsplit(sacc[2 * jj + 1][2], sacc[2 * jj + 1][3], pla[jj][3]);
    }

    // ---- O += P V (bf16x3; V via ldmatrix.trans) ----
#pragma unroll
    for (int dc = 0; dc < 8; ++dc) {
#pragma unroll
      for (int jj = 0; jj < 4; ++jj) {
        uint32_t bv[4], bvl_[4];
        const uint32_t vd = vAddr + (uint32_t)(jj * 16 * kAPad * 2) + dc * 32;
        ldsm4t(bv, vd);
        ldsm4t(bvl_, vd + kTileB);
        mma_bf16(o[2 * dc], pha[jj], bv[0], bv[1]);
        mma_bf16(o[2 * dc], pha[jj], bvl_[0], bvl_[1]);
        mma_bf16(o[2 * dc], pla[jj], bv[0], bv[1]);
        mma_bf16(o[2 * dc + 1], pha[jj], bv[2], bv[3]);
        mma_bf16(o[2 * dc + 1], pha[jj], bvl_[2], bvl_[3]);
        mma_bf16(o[2 * dc + 1], pla[jj], bv[2], bv[3]);
      }
    }
  }

  // ---- epilogue: normalize; write bf16 hi/lo as GEMM2's A ----
  const float i0 = 1.f / lrun0, i1 = 1.f / lrun1;
  const int row0 = q0 + (wid << 4) + g;
#pragma unroll
  for (int t = 0; t < 16; ++t) {
    const int d = (h << 7) + (t << 3) + (t4 << 1);
    uint32_t lo;
    uint32_t hi = packsplit(o[t][0] * i0, o[t][1] * i0, lo);
    *(uint32_t*)(oh + (size_t)row0 * kQS + d) = hi;
    *(uint32_t*)(ol + (size_t)row0 * kQS + d) = lo;
    hi = packsplit(o[t][2] * i1, o[t][3] * i1, lo);
    *(uint32_t*)(oh + (size_t)(row0 + 8) * kQS + d) = hi;
    *(uint32_t*)(ol + (size_t)(row0 + 8) * kQS + d) = lo;
  }
}

// =====================================================================
// launch
// =====================================================================
extern "C" void kernel_launch(void* const* d_in, const int* in_sizes, int n_in,
                              void* d_out, int out_size) {
  const int*   positions = (const int*)d_in[0];
  const float* hidden    = (const float*)d_in[1];
  const float* wqkv      = (const float*)d_in[2];
  const float* wo        = (const float*)d_in[3];
  float*       out       = (float*)d_out;

  void *p_qkv, *p_ah, *p_al, *p_b1h, *p_b1l, *p_b2h, *p_b2l;
  void *p_qh, *p_ql, *p_kh, *p_kl, *p_vh, *p_vl;
  cudaGetSymbolAddress(&p_qkv, g_qkv);
  cudaGetSymbolAddress(&p_ah, g_ah);
  cudaGetSymbolAddress(&p_al, g_al);
  cudaGetSymbolAddress(&p_b1h, g_b1h);
  cudaGetSymbolAddress(&p_b1l, g_b1l);
  cudaGetSymbolAddress(&p_b2h, g_b2h);
  cudaGetSymbolAddress(&p_b2l, g_b2l);
  cudaGetSymbolAddress(&p_qh, g_qh);
  cudaGetSymbolAddress(&p_ql, g_ql);
  cudaGetSymbolAddress(&p_kh, g_kh);
  cudaGetSymbolAddress(&p_kl, g_kl);
  cudaGetSymbolAddress(&p_vh, g_vh);
  cudaGetSymbolAddress(&p_vl, g_vl);

  float* qkv = (float*)p_qkv;
  __nv_bfloat16* ah = (__nv_bfloat16*)p_ah;
  __nv_bfloat16* al = (__nv_bfloat16*)p_al;
  __nv_bfloat16* b1h = (__nv_bfloat16*)p_b1h;
  __nv_bfloat16* b1l = (__nv_bfloat16*)p_b1l;
  __nv_bfloat16* b2h = (__nv_bfloat16*)p_b2h;
  __nv_bfloat16* b2l = (__nv_bfloat16*)p_b2l;
  __nv_bfloat16* qh = (__nv_bfloat16*)p_qh;
  __nv_bfloat16* ql = (__nv_bfloat16*)p_ql;
  __nv_bfloat16* kh = (__nv_bfloat16*)p_kh;
  __nv_bfloat16* kl = (__nv_bfloat16*)p_kl;
  __nv_bfloat16* vh = (__nv_bfloat16*)p_vh;
  __nv_bfloat16* vl = (__nv_bfloat16*)p_vl;

  constexpr int kAttnSmem = 6 * kATile * 2;  // 104448 B
  cudaFuncSetAttribute(attn_mma_kernel,
                       cudaFuncAttributeMaxDynamicSharedMemorySize, kAttnSmem);

  // QKV projection
  split_kernel<<<kT * kH / 4 / 256, 256>>>(hidden, ah, al, kT * kH / 4);
  transpose_split_kernel<<<dim3(kQKV / 32, kH / 32), dim3(32, 8)>>>(
      wqkv, b1h, b1l, kH, kQKV);
  gemm_mma_kernel<<<dim3(kQKV / 128, kT / 128), 256>>>(
      ah, al, b1h, b1l, qkv, kQKV);

  // RoPE, then split q/k/v into bf16 hi/lo attention layouts
  const int ropeTot = kT * (kNH + kNKV) * 64;
  rope_kernel<<<(ropeTot + 255) / 256, 256>>>(positions);
  qsplit_kernel<<<kT * kQS / 4 / 256, 256>>>(qkv, qh, ql);
  kvsplit_kernel<<<kT * 1024 / 4 / 256, 256>>>(qkv, kh, kl, vh, vl);

  // Attention (writes GEMM2's A hi/lo directly)
  attn_mma_kernel<<<dim3(kNH, kT / 64), 128, kAttnSmem>>>(
      qh, ql, kh, kl, vh, vl, ah, al);

  // Output projection
  transpose_split_kernel<<<dim3(kQS / 32, kH / 32), dim3(32, 8)>>>(
      wo, b2h, b2l, kH, kQS);
  gemm_mma_kernel<<<dim3(kQS / 128, kT / 128), 256>>>(
      ah, al, b2h, b2l, out, kQS);
}

// round 9
// speedup vs baseline: 2.7719x; 1.0145x over previous
#include <cuda_runtime.h>
#include <cuda_bf16.h>
#include <math.h>
#include <stdint.h>

// ----------------- problem constants -----------------
constexpr int kT    = 2048;
constexpr int kH    = 4096;
constexpr int kNH   = 32;
constexpr int kNKV  = 8;
constexpr int kHD   = 128;
constexpr int kQKV  = 6144;
constexpr int kQS   = 4096;
constexpr int kKOff = 4096;
constexpr int kVOff = 5120;

// ----------------- scratch (no allocations allowed) -----------------
__device__ float g_qkv[kT * kQKV];
__device__ __align__(16) __nv_bfloat16 g_ah[kT * kH];     // GEMM A hi
__device__ __align__(16) __nv_bfloat16 g_al[kT * kH];     // GEMM A lo
__device__ __align__(16) __nv_bfloat16 g_b1h[kQKV * kH];  // w_qkv^T hi [N,K]
__device__ __align__(16) __nv_bfloat16 g_b1l[kQKV * kH];
__device__ __align__(16) __nv_bfloat16 g_b2h[kQS * kH];   // w_o^T hi [N,K]
__device__ __align__(16) __nv_bfloat16 g_b2l[kQS * kH];
__device__ __align__(16) __nv_bfloat16 g_qh[kNH * kT * kHD];   // q scaled hi [h][t][d]
__device__ __align__(16) __nv_bfloat16 g_ql[kNH * kT * kHD];
__device__ __align__(16) __nv_bfloat16 g_kh[kNKV * kT * kHD];  // k hi [kv][t][d]
__device__ __align__(16) __nv_bfloat16 g_kl[kNKV * kT * kHD];
__device__ __align__(16) __nv_bfloat16 g_vh[kNKV * kT * kHD];
__device__ __align__(16) __nv_bfloat16 g_vl[kNKV * kT * kHD];

// ================= low-level helpers =================
__device__ __forceinline__ uint32_t smem_u32(const void* p) {
  uint32_t a;
  asm("{ .reg .u64 t; cvta.to.shared.u64 t, %1; cvt.u32.u64 %0, t; }"
      : "=r"(a) : "l"(p));
  return a;
}
__device__ __forceinline__ void cp16(uint32_t saddr, const void* g) {
  asm volatile("cp.async.cg.shared.global [%0], [%1], 16;"
               :: "r"(saddr), "l"(g));
}
#define CP_COMMIT() asm volatile("cp.async.commit_group;" ::: "memory")
#define CP_WAIT1()  asm volatile("cp.async.wait_group 1;" ::: "memory")
#define CP_WAIT0()  asm volatile("cp.async.wait_group 0;" ::: "memory")

__device__ __forceinline__ void ldsm4(uint32_t* r, uint32_t addr) {
  asm volatile("ldmatrix.sync.aligned.m8n8.x4.shared.b16 {%0,%1,%2,%3}, [%4];"
               : "=r"(r[0]), "=r"(r[1]), "=r"(r[2]), "=r"(r[3]) : "r"(addr));
}
__device__ __forceinline__ void ldsm4t(uint32_t* r, uint32_t addr) {
  asm volatile("ldmatrix.sync.aligned.m8n8.x4.trans.shared.b16 {%0,%1,%2,%3}, [%4];"
               : "=r"(r[0]), "=r"(r[1]), "=r"(r[2]), "=r"(r[3]) : "r"(addr));
}
__device__ __forceinline__ void mma_bf16(float* c, const uint32_t* a,
                                         uint32_t b0, uint32_t b1) {
  asm volatile(
      "mma.sync.aligned.m16n8k16.row.col.f32.bf16.bf16.f32 "
      "{%0,%1,%2,%3}, {%4,%5,%6,%7}, {%8,%9}, {%0,%1,%2,%3};"
      : "+f"(c[0]), "+f"(c[1]), "+f"(c[2]), "+f"(c[3])
      : "r"(a[0]), "r"(a[1]), "r"(a[2]), "r"(a[3]), "r"(b0), "r"(b1));
}
__device__ __forceinline__ uint32_t packsplit(float x, float y, uint32_t& lo) {
  __nv_bfloat16 hx = __float2bfloat16_rn(x);
  __nv_bfloat16 hy = __float2bfloat16_rn(y);
  __nv_bfloat162 hp(hx, hy);
  __nv_bfloat162 lp(__float2bfloat16_rn(x - __bfloat162float(hx)),
                    __float2bfloat16_rn(y - __bfloat162float(hy)));
  lo = *(uint32_t*)&lp;
  return *(uint32_t*)&hp;
}

// =====================================================================
// Conversion kernels
// =====================================================================
__global__ void split_kernel(const float* __restrict__ X,
                             __nv_bfloat16* __restrict__ H,
                             __nv_bfloat16* __restrict__ L, int total4) {
  const int i = blockIdx.x * blockDim.x + threadIdx.x;
  if (i >= total4) return;
  const float4 v = ((const float4*)X)[i];
  uint32_t l0, l1;
  const uint32_t h0 = packsplit(v.x, v.y, l0);
  const uint32_t h1 = packsplit(v.z, v.w, l1);
  ((uint2*)H)[i] = make_uint2(h0, h1);
  ((uint2*)L)[i] = make_uint2(l0, l1);
}

__global__ void transpose_split_kernel(const float* __restrict__ W,
                                       __nv_bfloat16* __restrict__ Th,
                                       __nv_bfloat16* __restrict__ Tl,
                                       int K, int N) {
  __shared__ float t[32][33];
  const int n0 = blockIdx.x * 32, k0 = blockIdx.y * 32;
  const int tx = threadIdx.x, ty = threadIdx.y;
#pragma unroll
  for (int j = 0; j < 4; ++j)
    t[ty + 8 * j][tx] = W[(size_t)(k0 + ty + 8 * j) * N + n0 + tx];
  __syncthreads();
#pragma unroll
  for (int j = 0; j < 4; ++j) {
    const int n = ty + 8 * j;
    const float v = t[tx][n];
    const __nv_bfloat16 h = __float2bfloat16_rn(v);
    const size_t o = (size_t)(n0 + n) * K + k0 + tx;
    Th[o] = h;
    Tl[o] = __float2bfloat16_rn(v - __bfloat162float(h));
  }
}

__global__ void qsplit_kernel(const float* __restrict__ qkv,
                              __nv_bfloat16* __restrict__ qh,
                              __nv_bfloat16* __restrict__ ql) {
  const int i = blockIdx.x * blockDim.x + threadIdx.x;
  if (i >= kT * kQS / 4) return;
  const int e = i * 4;
  const int t = e >> 12;
  const int rem = e & 4095;
  const int hh = rem >> 7, d = rem & 127;
  const float4 v = *(const float4*)(qkv + (size_t)t * kQKV + rem);
  constexpr float sc = 0.08838834764831845f;
  uint32_t l0, l1;
  const uint32_t h0 = packsplit(v.x * sc, v.y * sc, l0);
  const uint32_t h1 = packsplit(v.z * sc, v.w * sc, l1);
  const size_t o = ((size_t)hh * kT + t) * kHD + d;
  *(uint2*)(qh + o) = make_uint2(h0, h1);
  *(uint2*)(ql + o) = make_uint2(l0, l1);
}

__global__ void kvsplit_kernel(const float* __restrict__ qkv,
                               __nv_bfloat16* __restrict__ kh,
                               __nv_bfloat16* __restrict__ kl,
                               __nv_bfloat16* __restrict__ vh,
                               __nv_bfloat16* __restrict__ vl) {
  const int i = blockIdx.x * blockDim.x + threadIdx.x;
  if (i >= kT * 1024 / 4) return;
  const int e = i * 4;
  const int t = e >> 10;
  const int rem = e & 1023;
  const int kv = rem >> 7, d = rem & 127;
  const size_t o = ((size_t)kv * kT + t) * kHD + d;
  const float4 kf = *(const float4*)(qkv + (size_t)t * kQKV + kKOff + rem);
  const float4 vf = *(const float4*)(qkv + (size_t)t * kQKV + kVOff + rem);
  uint32_t l0, l1;
  uint32_t h0 = packsplit(kf.x, kf.y, l0);
  uint32_t h1 = packsplit(kf.z, kf.w, l1);
  *(uint2*)(kh + o) = make_uint2(h0, h1);
  *(uint2*)(kl + o) = make_uint2(l0, l1);
  h0 = packsplit(vf.x, vf.y, l0);
  h1 = packsplit(vf.z, vf.w, l1);
  *(uint2*)(vh + o) = make_uint2(h0, h1);
  *(uint2*)(vl + o) = make_uint2(l0, l1);
}

// =====================================================================
// bf16x3 GEMM on mma.sync, cp.async 2-stage pipeline.
// C[M,NT] = A[M,4096] @ B^T[N,K]. Block 128x128, BK=32, 8 warps.
// Dynamic smem: 2 stages x 4 tiles x 10240B = 81920 B.
// =====================================================================
constexpr int kLds = 40;                       // halves per row
constexpr int kGTileB = 128 * kLds * 2;        // 10240 B per tile
constexpr int kGStageB = 4 * kGTileB;          // 40960 B per stage
constexpr int kGemmSmem = 2 * kGStageB;        // 81920 B

__global__ __launch_bounds__(256)
void gemm_mma_kernel(const __nv_bfloat16* __restrict__ Ah,
                     const __nv_bfloat16* __restrict__ Al,
                     const __nv_bfloat16* __restrict__ Bh,
                     const __nv_bfloat16* __restrict__ Bl,
                     float* __restrict__ C, int NT) {
  constexpr int K = kH;
  constexpr int BK = 32;
  constexpr int NST = K / BK;  // 128
  extern __shared__ __align__(16) __nv_bfloat16 gsm[];
  const uint32_t base = smem_u32(gsm);

  const int tid = threadIdx.x;
  const int wid = tid >> 5, lane = tid & 31;
  const int m0 = blockIdx.y << 7;
  const int n0 = blockIdx.x << 7;
  const int wm = (wid >> 2) << 6;
  const int wn = (wid & 3) << 5;

  const int lr = tid >> 2, ls = tid & 3;
  const uint32_t so0 = (uint32_t)(lr * 80 + ls * 16);
  const uint32_t so1 = (uint32_t)((lr + 64) * 80 + ls * 16);

  float acc[4][4][4];
#pragma unroll
  for (int i = 0; i < 4; ++i)
#pragma unroll
    for (int j = 0; j < 4; ++j)
#pragma unroll
      for (int q = 0; q < 4; ++q) acc[i][j][q] = 0.f;

  const size_t aOff0 = (size_t)(m0 + lr) * K + ls * 8;
  const size_t aOff1 = aOff0 + (size_t)64 * K;
  const size_t bOff0 = (size_t)(n0 + lr) * K + ls * 8;
  const size_t bOff1 = bOff0 + (size_t)64 * K;

#define GLOAD(st, kc) do {                                        \
    const uint32_t sb = base + (uint32_t)((st) * kGStageB);      \
    cp16(sb + so0,                Ah + aOff0 + (kc));            \
    cp16(sb + so1,                Ah + aOff1 + (kc));            \
    cp16(sb + kGTileB + so0,      Al + aOff0 + (kc));            \
    cp16(sb + kGTileB + so1,      Al + aOff1 + (kc));            \
    cp16(sb + 2 * kGTileB + so0,  Bh + bOff0 + (kc));            \
    cp16(sb + 2 * kGTileB + so1,  Bh + bOff1 + (kc));            \
    cp16(sb + 3 * kGTileB + so0,  Bl + bOff0 + (kc));            \
    cp16(sb + 3 * kGTileB + so1,  Bl + bOff1 + (kc));            \
  } while (0)

  GLOAD(0, 0);
  CP_COMMIT();
  GLOAD(1, BK);
  CP_COMMIT();

#pragma unroll 1
  for (int kt = 0; kt < NST; ++kt) {
    if (kt < NST - 2) CP_WAIT1(); else CP_WAIT0();
    __syncthreads();

    const uint32_t sb = base + (uint32_t)((kt & 1) * kGStageB);
#pragma unroll
    for (int kh = 0; kh < 2; ++kh) {
      const int slot = kh * 2 + (lane >> 4);
      const int arow = wm + (lane & 15);
      const int brow = wn + (lane & 15);

      uint32_t ah[4][4], al[4][4];
#pragma unroll
      for (int i = 0; i < 4; ++i) {
        const uint32_t ad = sb + (uint32_t)((arow + 16 * i) * 80 + slot * 16);
        ldsm4(ah[i], ad);
        ldsm4(al[i], ad + kGTileB);
      }
      uint32_t bh[2][4], bl[2][4];
#pragma unroll
      for (int p = 0; p < 2; ++p) {
        const uint32_t bd = sb + (uint32_t)(2 * kGTileB) +
                            (uint32_t)((brow + 16 * p) * 80 + slot * 16);
        ldsm4(bh[p], bd);
        ldsm4(bl[p], bd + kGTileB);
      }
#pragma unroll
      for (int i = 0; i < 4; ++i)
#pragma unroll
        for (int j = 0; j < 4; ++j) {
          const int p = j >> 1, w = j & 1;
          mma_bf16(acc[i][j], ah[i], bh[p][w], bh[p][2 + w]);
          mma_bf16(acc[i][j], ah[i], bl[p][w], bl[p][2 + w]);
          mma_bf16(acc[i][j], al[i], bh[p][w], bh[p][2 + w]);
        }
    }
    __syncthreads();
    if (kt + 2 < NST) {
      GLOAD(kt & 1, (kt + 2) * BK);
      CP_COMMIT();
    }
  }
#undef GLOAD

  const int g = lane >> 2, t4 = lane & 3;
#pragma unroll
  for (int i = 0; i < 4; ++i) {
    const int r0 = m0 + wm + 16 * i + g;
#pragma unroll
    for (int j = 0; j < 4; ++j) {
      const int col = n0 + wn + 8 * j + 2 * t4;
      *(float2*)(C + (size_t)r0 * NT + col) =
          make_float2(acc[i][j][0], acc[i][j][1]);
      *(float2*)(C + (size_t)(r0 + 8) * NT + col) =
          make_float2(acc[i][j][2], acc[i][j][3]);
    }
  }
}

// =====================================================================
// RoPE in place (fp32 exp2f inv_freq)
// =====================================================================
__global__ void rope_kernel(const int* __restrict__ pos) {
  const int idx = blockIdx.x * blockDim.x + threadIdx.x;
  const int totq = kT * kNH * 64;
  const int tot = totq + kT * kNKV * 64;
  if (idx >= tot) return;

  float* base;
  int t, i;
  if (idx < totq) {
    t = idx / (kNH * 64);
    const int r = idx - t * (kNH * 64);
    i = r & 63;
    base = g_qkv + (size_t)t * kQKV + (r >> 6) * kHD;
  } else {
    const int j = idx - totq;
    t = j / (kNKV * 64);
    const int r = j - t * (kNKV * 64);
    i = r & 63;
    base = g_qkv + (size_t)t * kQKV + kKOff + (r >> 6) * kHD;
  }
  constexpr float kNegLog2Theta64 = -0.29580667120644826f;
  const float inv = exp2f((float)i * kNegLog2Theta64);
  const float f = (float)pos[t] * inv;
  float sn, cs;
  sincosf(f, &sn, &cs);
  const float x1 = base[i], x2 = base[i + 64];
  base[i] = x1 * cs - x2 * sn;
  base[i + 64] = x2 * cs + x1 * sn;
}

// =====================================================================
// Flash attention on mma.sync, bf16x3 (KV fill via cp.async).
// =====================================================================
constexpr int kAPad  = 136;
constexpr int kATile = 64 * kAPad;
constexpr uint32_t kTileB = kATile * 2;

__global__ __launch_bounds__(128)
void attn_mma_kernel(const __nv_bfloat16* __restrict__ qh,
                     const __nv_bfloat16* __restrict__ ql,
                     const __nv_bfloat16* __restrict__ kh,
                     const __nv_bfloat16* __restrict__ kl,
                     const __nv_bfloat16* __restrict__ vh,
                     const __nv_bfloat16* __restrict__ vl,
                     __nv_bfloat16* __restrict__ oh,
                     __nv_bfloat16* __restrict__ ol) {
  extern __shared__ __nv_bfloat16 sma[];
  const int h = blockIdx.x;
  const int qb = (int)gridDim.y - 1 - (int)blockIdx.y;
  const int kvi = h >> 2;
  const int tid = threadIdx.x;
  const int wid = tid >> 5, lane = tid & 31;
  const int q0 = qb << 6;
  const uint32_t base = smem_u32(sma);
  const int g = lane >> 2, t4 = lane & 3;

  {
    const __nv_bfloat16* Qh = qh + ((size_t)h * kT + q0) * kHD;
    const __nv_bfloat16* Ql = ql + ((size_t)h * kT + q0) * kHD;
#pragma unroll
    for (int j = 0; j < 8; ++j) {
      const int idx = tid + (j << 7);
      const int r = idx >> 4, s = idx & 15;
      const int so = r * kAPad + s * 8;
      *(uint4*)(sma + so)          = *(const uint4*)(Qh + r * 128 + s * 8);
      *(uint4*)(sma + kATile + so) = *(const uint4*)(Ql + r * 128 + s * 8);
    }
  }

  float o[16][4];
#pragma unroll
  for (int t = 0; t < 16; ++t)
#pragma unroll
    for (int q = 0; q < 4; ++q) o[t][q] = 0.f;
  float mrun0 = -1e30f, mrun1 = -1e30f, lrun0 = 0.f, lrun1 = 0.f;

  const uint32_t aAddr =
      base + 2u * (uint32_t)(((wid << 4) + (lane & 15)) * kAPad + ((lane >> 4) << 3));
  const uint32_t kAddr =
      base + 2u * kTileB +
      2u * (uint32_t)((lane & 15) * kAPad + ((lane >> 4) << 3));
  const uint32_t vAddr =
      base + 4u * kTileB +
      2u * (uint32_t)((lane & 15) * kAPad + ((lane >> 4) << 3));

#pragma unroll 1
  for (int kb = 0; kb <= qb; ++kb) {
    __syncthreads();
    const size_t kvoff = ((size_t)kvi * kT + ((size_t)kb << 6)) * kHD;
#pragma unroll
    for (int j = 0; j < 8; ++j) {
      const int idx = tid + (j << 7);
      const int r = idx >> 4, s = idx & 15;
      const uint32_t so = (uint32_t)((r * kAPad + s * 8) * 2);
      const size_t go = kvoff + r * 128 + s * 8;
      cp16(base + 2u * kTileB + so, kh + go);
      cp16(base + 3u * kTileB + so, kl + go);
      cp16(base + 4u * kTileB + so, vh + go);
      cp16(base + 5u * kTileB + so, vl + go);
    }
    CP_COMMIT();
    CP_WAIT0();
    __syncthreads();

    // ---- S = Q K^T (bf16x3) ----
    float sacc[8][4];
#pragma unroll
    for (int j = 0; j < 8; ++j)
#pragma unroll
      for (int q = 0; q < 4; ++q) sacc[j][q] = 0.f;

#pragma unroll
    for (int kc = 0; kc < 8; ++kc) {
      uint32_t aq[4], aql_[4];
      const uint32_t ad = aAddr + kc * 32;
      ldsm4(aq, ad);
      ldsm4(aql_, ad + kTileB);
#pragma unroll
      for (int p = 0; p < 4; ++p) {
        uint32_t bk[4], bkl_[4];
        const uint32_t bd = kAddr + (uint32_t)(p * 16 * kAPad * 2) + kc * 32;
        ldsm4(bk, bd);
        ldsm4(bkl_, bd + kTileB);
#pragma unroll
        for (int w2 = 0; w2 < 2; ++w2) {
          const int j = p * 2 + w2;
          mma_bf16(sacc[j], aq, bk[w2], bk[2 + w2]);
          mma_bf16(sacc[j], aq, bkl_[w2], bkl_[2 + w2]);
          mma_bf16(sacc[j], aql_, bk[w2], bk[2 + w2]);
        }
      }
    }

    if (kb == qb) {
      const int r0 = (wid << 4) + g;
#pragma unroll
      for (int j = 0; j < 8; ++j) {
        const int c = (j << 3) + (t4 << 1);
        if (c > r0)         sacc[j][0] = -1e30f;
        if (c + 1 > r0)     sacc[j][1] = -1e30f;
        if (c > r0 + 8)     sacc[j][2] = -1e30f;
        if (c + 1 > r0 + 8) sacc[j][3] = -1e30f;
      }
    }

    float mx0 = -1e30f, mx1 = -1e30f;
#pragma unroll
    for (int j = 0; j < 8; ++j) {
      mx0 = fmaxf(mx0, fmaxf(sacc[j][0], sacc[j][1]));
      mx1 = fmaxf(mx1, fmaxf(sacc[j][2], sacc[j][3]));
    }
    mx0 = fmaxf(mx0, __shfl_xor_sync(0xffffffffu, mx0, 1));
    mx0 = fmaxf(mx0, __shfl_xor_sync(0xffffffffu, mx0, 2));
    mx1 = fmaxf(mx1, __shfl_xor_sync(0xffffffffu, mx1, 1));
    mx1 = fmaxf(mx1, __shfl_xor_sync(0xffffffffu, mx1, 2));
    const float mn0 = fmaxf(mrun0, mx0), mn1 = fmaxf(mrun1, mx1);
    const float f0 = __expf(mrun0 - mn0), f1 = __expf(mrun1 - mn1);
    float rs0 = 0.f, rs1 = 0.f;
#pragma unroll
    for (int j = 0; j < 8; ++j) {
      sacc[j][0] = __expf(sacc[j][0] - mn0);
      sacc[j][1] = __expf(sacc[j][1] - mn0);
      sacc[j][2] = __expf(sacc[j][2] - mn1);
      sacc[j][3] = __expf(sacc[j][3] - mn1);
      rs0 += sacc[j][0] + sacc[j][1];
      rs1 += sacc[j][2] + sacc[j][3];
    }
    rs0 += __shfl_xor_sync(0xffffffffu, rs0, 1);
    rs0 += __shfl_xor_sync(0xffffffffu, rs0, 2);
    rs1 += __shfl_xor_sync(0xffffffffu, rs1, 1);
    rs1 += __shfl_xor_sync(0xffffffffu, rs1, 2);
    lrun0 = lrun0 * f0 + rs0;
    lrun1 = lrun1 * f1 + rs1;
    mrun0 = mn0;
    mrun1 = mn1;
#pragma unroll
    for (int t = 0; t < 16; ++t) {
      o[t][0] *= f0; o[t][1] *= f0; o[t][2] *= f1; o[t][3] *= f1;
    }

    uint32_t pha[4][4], pla[4][4];
#pragma unroll
    for (int jj = 0; jj < 4; ++jj) {
      pha[jj][0] = packsplit(sacc[2 * jj][0], sacc[2 * jj][1], pla[jj][0]);
      pha[jj][1] = packsplit(sacc[2 * jj][2], sacc[2 * jj][3], pla[jj][1]);
      pha[jj][2] = packsplit(sacc[2 * jj + 1][0], sacc[2 * jj + 1][1], pla[jj][2]);
      pha[jj][3] = packsplit(sacc[2 * jj + 1][2], sacc[2 * jj + 1][3], pla[jj][3]);
    }

#pragma unroll
    for (int dc = 0; dc < 8; ++dc) {
#pragma unroll
      for (int jj = 0; jj < 4; ++jj) {
        uint32_t bv[4], bvl_[4];
        const uint32_t vd = vAddr + (uint32_t)(jj * 16 * kAPad * 2) + dc * 32;
        ldsm4t(bv, vd);
        ldsm4t(bvl_, vd + kTileB);
        mma_bf16(o[2 * dc], pha[jj], bv[0], bv[1]);
        mma_bf16(o[2 * dc], pha[jj], bvl_[0], bvl_[1]);
        mma_bf16(o[2 * dc], pla[jj], bv[0], bv[1]);
        mma_bf16(o[2 * dc + 1], pha[jj], bv[2], bv[3]);
        mma_bf16(o[2 * dc + 1], pha[jj], bvl_[2], bvl_[3]);
        mma_bf16(o[2 * dc + 1], pla[jj], bv[2], bv[3]);
      }
    }
  }

  const float i0 = 1.f / lrun0, i1 = 1.f / lrun1;
  const int row0 = q0 + (wid << 4) + g;
#pragma unroll
  for (int t = 0; t < 16; ++t) {
    const int d = (h << 7) + (t << 3) + (t4 << 1);
    uint32_t lo;
    uint32_t hi = packsplit(o[t][0] * i0, o[t][1] * i0, lo);
    *(uint32_t*)(oh + (size_t)row0 * kQS + d) = hi;
    *(uint32_t*)(ol + (size_t)row0 * kQS + d) = lo;
    hi = packsplit(o[t][2] * i1, o[t][3] * i1, lo);
    *(uint32_t*)(oh + (size_t)(row0 + 8) * kQS + d) = hi;
    *(uint32_t*)(ol + (size_t)(row0 + 8) * kQS + d) = lo;
  }
}

// =====================================================================
// launch
// =====================================================================
extern "C" void kernel_launch(void* const* d_in, const int* in_sizes, int n_in,
                              void* d_out, int out_size) {
  const int*   positions = (const int*)d_in[0];
  const float* hidden    = (const float*)d_in[1];
  const float* wqkv      = (const float*)d_in[2];
  const float* wo        = (const float*)d_in[3];
  float*       out       = (float*)d_out;

  void *p_qkv, *p_ah, *p_al, *p_b1h, *p_b1l, *p_b2h, *p_b2l;
  void *p_qh, *p_ql, *p_kh, *p_kl, *p_vh, *p_vl;
  cudaGetSymbolAddress(&p_qkv, g_qkv);
  cudaGetSymbolAddress(&p_ah, g_ah);
  cudaGetSymbolAddress(&p_al, g_al);
  cudaGetSymbolAddress(&p_b1h, g_b1h);
  cudaGetSymbolAddress(&p_b1l, g_b1l);
  cudaGetSymbolAddress(&p_b2h, g_b2h);
  cudaGetSymbolAddress(&p_b2l, g_b2l);
  cudaGetSymbolAddress(&p_qh, g_qh);
  cudaGetSymbolAddress(&p_ql, g_ql);
  cudaGetSymbolAddress(&p_kh, g_kh);
  cudaGetSymbolAddress(&p_kl, g_kl);
  cudaGetSymbolAddress(&p_vh, g_vh);
  cudaGetSymbolAddress(&p_vl, g_vl);

  float* qkv = (float*)p_qkv;
  __nv_bfloat16* ah = (__nv_bfloat16*)p_ah;
  __nv_bfloat16* al = (__nv_bfloat16*)p_al;
  __nv_bfloat16* b1h = (__nv_bfloat16*)p_b1h;
  __nv_bfloat16* b1l = (__nv_bfloat16*)p_b1l;
  __nv_bfloat16* b2h = (__nv_bfloat16*)p_b2h;
  __nv_bfloat16* b2l = (__nv_bfloat16*)p_b2l;
  __nv_bfloat16* qh = (__nv_bfloat16*)p_qh;
  __nv_bfloat16* ql = (__nv_bfloat16*)p_ql;
  __nv_bfloat16* kh = (__nv_bfloat16*)p_kh;
  __nv_bfloat16* kl = (__nv_bfloat16*)p_kl;
  __nv_bfloat16* vh = (__nv_bfloat16*)p_vh;
  __nv_bfloat16* vl = (__nv_bfloat16*)p_vl;

  constexpr int kAttnSmem = 6 * kATile * 2;  // 104448 B
  cudaFuncSetAttribute(attn_mma_kernel,
                       cudaFuncAttributeMaxDynamicSharedMemorySize, kAttnSmem);
  cudaFuncSetAttribute(gemm_mma_kernel,
                       cudaFuncAttributeMaxDynamicSharedMemorySize, kGemmSmem);

  // QKV projection
  split_kernel<<<kT * kH / 4 / 256, 256>>>(hidden, ah, al, kT * kH / 4);
  transpose_split_kernel<<<dim3(kQKV / 32, kH / 32), dim3(32, 8)>>>(
      wqkv, b1h, b1l, kH, kQKV);
  gemm_mma_kernel<<<dim3(kQKV / 128, kT / 128), 256, kGemmSmem>>>(
      ah, al, b1h, b1l, qkv, kQKV);

  // RoPE, then split q/k/v into bf16 hi/lo attention layouts
  const int ropeTot = kT * (kNH + kNKV) * 64;
  rope_kernel<<<(ropeTot + 255) / 256, 256>>>(positions);
  qsplit_kernel<<<kT * kQS / 4 / 256, 256>>>(qkv, qh, ql);
  kvsplit_kernel<<<kT * 1024 / 4 / 256, 256>>>(qkv, kh, kl, vh, vl);

  // Attention (writes GEMM2's A hi/lo directly)
  attn_mma_kernel<<<dim3(kNH, kT / 64), 128, kAttnSmem>>>(
      qh, ql, kh, kl, vh, vl, ah, al);

  // Output projection
  transpose_split_kernel<<<dim3(kQS / 32, kH / 32), dim3(32, 8)>>>(
      wo, b2h, b2l, kH, kQS);
  gemm_mma_kernel<<<dim3(kQS / 128, kT / 128), 256, kGemmSmem>>>(
      ah, al, b2h, b2l, out, kQS);
}

// round 10
// speedup vs baseline: 2.8385x; 1.0240x over previous
#include <cuda_runtime.h>
#include <cuda_bf16.h>
#include <cuda_fp16.h>
#include <math.h>
#include <stdint.h>

// ----------------- problem constants -----------------
constexpr int kT    = 2048;
constexpr int kH    = 4096;
constexpr int kNH   = 32;
constexpr int kNKV  = 8;
constexpr int kHD   = 128;
constexpr int kQKV  = 6144;
constexpr int kQS   = 4096;
constexpr int kKOff = 4096;
constexpr int kVOff = 5120;

// ----------------- scratch (no allocations allowed) -----------------
__device__ float g_qkv[kT * kQKV];
__device__ __align__(16) __nv_bfloat16 g_ah[kT * kH];     // GEMM A hi
__device__ __align__(16) __nv_bfloat16 g_al[kT * kH];     // GEMM A lo
__device__ __align__(16) __nv_bfloat16 g_b1h[kQKV * kH];  // w_qkv^T hi [N,K]
__device__ __align__(16) __nv_bfloat16 g_b1l[kQKV * kH];
__device__ __align__(16) __nv_bfloat16 g_b2h[kQS * kH];   // w_o^T hi [N,K]
__device__ __align__(16) __nv_bfloat16 g_b2l[kQS * kH];
__device__ __align__(16) __nv_bfloat16 g_qh[kNH * kT * kHD];   // q scaled hi [h][t][d]
__device__ __align__(16) __nv_bfloat16 g_ql[kNH * kT * kHD];
__device__ __align__(16) __nv_bfloat16 g_kh[kNKV * kT * kHD];  // k hi [kv][t][d]
__device__ __align__(16) __nv_bfloat16 g_kl[kNKV * kT * kHD];
__device__ __align__(16) __half       g_vh[kNKV * kT * kHD];   // v fp16 hi
__device__ __align__(16) __half       g_vl[kNKV * kT * kHD];   // v fp16 lo

// ================= low-level helpers =================
__device__ __forceinline__ uint32_t smem_u32(const void* p) {
  uint32_t a;
  asm("{ .reg .u64 t; cvta.to.shared.u64 t, %1; cvt.u32.u64 %0, t; }"
      : "=r"(a) : "l"(p));
  return a;
}
__device__ __forceinline__ void cp16(uint32_t saddr, const void* g) {
  asm volatile("cp.async.cg.shared.global [%0], [%1], 16;"
               :: "r"(saddr), "l"(g));
}
#define CP_COMMIT() asm volatile("cp.async.commit_group;" ::: "memory")
#define CP_WAIT1()  asm volatile("cp.async.wait_group 1;" ::: "memory")
#define CP_WAIT0()  asm volatile("cp.async.wait_group 0;" ::: "memory")

__device__ __forceinline__ void ldsm4(uint32_t* r, uint32_t addr) {
  asm volatile("ldmatrix.sync.aligned.m8n8.x4.shared.b16 {%0,%1,%2,%3}, [%4];"
               : "=r"(r[0]), "=r"(r[1]), "=r"(r[2]), "=r"(r[3]) : "r"(addr));
}
__device__ __forceinline__ void ldsm4t(uint32_t* r, uint32_t addr) {
  asm volatile("ldmatrix.sync.aligned.m8n8.x4.trans.shared.b16 {%0,%1,%2,%3}, [%4];"
               : "=r"(r[0]), "=r"(r[1]), "=r"(r[2]), "=r"(r[3]) : "r"(addr));
}
__device__ __forceinline__ void mma_bf16(float* c, const uint32_t* a,
                                         uint32_t b0, uint32_t b1) {
  asm volatile(
      "mma.sync.aligned.m16n8k16.row.col.f32.bf16.bf16.f32 "
      "{%0,%1,%2,%3}, {%4,%5,%6,%7}, {%8,%9}, {%0,%1,%2,%3};"
      : "+f"(c[0]), "+f"(c[1]), "+f"(c[2]), "+f"(c[3])
      : "r"(a[0]), "r"(a[1]), "r"(a[2]), "r"(a[3]), "r"(b0), "r"(b1));
}
__device__ __forceinline__ void mma_fp16(float* c, const uint32_t* a,
                                         uint32_t b0, uint32_t b1) {
  asm volatile(
      "mma.sync.aligned.m16n8k16.row.col.f32.f16.f16.f32 "
      "{%0,%1,%2,%3}, {%4,%5,%6,%7}, {%8,%9}, {%0,%1,%2,%3};"
      : "+f"(c[0]), "+f"(c[1]), "+f"(c[2]), "+f"(c[3])
      : "r"(a[0]), "r"(a[1]), "r"(a[2]), "r"(a[3]), "r"(b0), "r"(b1));
}
__device__ __forceinline__ uint32_t packsplit(float x, float y, uint32_t& lo) {
  __nv_bfloat16 hx = __float2bfloat16_rn(x);
  __nv_bfloat16 hy = __float2bfloat16_rn(y);
  __nv_bfloat162 hp(hx, hy);
  __nv_bfloat162 lp(__float2bfloat16_rn(x - __bfloat162float(hx)),
                    __float2bfloat16_rn(y - __bfloat162float(hy)));
  lo = *(uint32_t*)&lp;
  return *(uint32_t*)&hp;
}
__device__ __forceinline__ uint32_t packsplit_h(float x, float y, uint32_t& lo) {
  __half hx = __float2half_rn(x), hy = __float2half_rn(y);
  __half2 hp(hx, hy);
  __half2 lp(__float2half_rn(x - __half2float(hx)),
             __float2half_rn(y - __half2float(hy)));
  lo = *(uint32_t*)&lp;
  return *(uint32_t*)&hp;
}
__device__ __forceinline__ uint32_t packh2(float x, float y) {
  __half2 h = __floats2half2_rn(x, y);
  return *(uint32_t*)&h;
}

// =====================================================================
// Conversion kernels
// =====================================================================
__global__ void split_kernel(const float* __restrict__ X,
                             __nv_bfloat16* __restrict__ H,
                             __nv_bfloat16* __restrict__ L, int total4) {
  const int i = blockIdx.x * blockDim.x + threadIdx.x;
  if (i >= total4) return;
  const float4 v = ((const float4*)X)[i];
  uint32_t l0, l1;
  const uint32_t h0 = packsplit(v.x, v.y, l0);
  const uint32_t h1 = packsplit(v.z, v.w, l1);
  ((uint2*)H)[i] = make_uint2(h0, h1);
  ((uint2*)L)[i] = make_uint2(l0, l1);
}

__global__ void transpose_split_kernel(const float* __restrict__ W,
                                       __nv_bfloat16* __restrict__ Th,
                                       __nv_bfloat16* __restrict__ Tl,
                                       int K, int N) {
  __shared__ float t[32][33];
  const int n0 = blockIdx.x * 32, k0 = blockIdx.y * 32;
  const int tx = threadIdx.x, ty = threadIdx.y;
#pragma unroll
  for (int j = 0; j < 4; ++j)
    t[ty + 8 * j][tx] = W[(size_t)(k0 + ty + 8 * j) * N + n0 + tx];
  __syncthreads();
#pragma unroll
  for (int j = 0; j < 4; ++j) {
    const int n = ty + 8 * j;
    const float v = t[tx][n];
    const __nv_bfloat16 h = __float2bfloat16_rn(v);
    const size_t o = (size_t)(n0 + n) * K + k0 + tx;
    Th[o] = h;
    Tl[o] = __float2bfloat16_rn(v - __bfloat162float(h));
  }
}

// q -> scaled hi/lo, layout [h][t][d]; scale folds 1/sqrt(128) * log2(e)
__global__ void qsplit_kernel(const float* __restrict__ qkv,
                              __nv_bfloat16* __restrict__ qh,
                              __nv_bfloat16* __restrict__ ql) {
  const int i = blockIdx.x * blockDim.x + threadIdx.x;
  if (i >= kT * kQS / 4) return;
  const int e = i * 4;
  const int t = e >> 12;
  const int rem = e & 4095;
  const int hh = rem >> 7, d = rem & 127;
  const float4 v = *(const float4*)(qkv + (size_t)t * kQKV + rem);
  constexpr float sc = 0.08838834764831845f * 1.4426950408889634f;
  uint32_t l0, l1;
  const uint32_t h0 = packsplit(v.x * sc, v.y * sc, l0);
  const uint32_t h1 = packsplit(v.z * sc, v.w * sc, l1);
  const size_t o = ((size_t)hh * kT + t) * kHD + d;
  *(uint2*)(qh + o) = make_uint2(h0, h1);
  *(uint2*)(ql + o) = make_uint2(l0, l1);
}

// k (bf16 hi/lo) and v (fp16 hi/lo), layout [kv][t][d]
__global__ void kvsplit_kernel(const float* __restrict__ qkv,
                               __nv_bfloat16* __restrict__ kh,
                               __nv_bfloat16* __restrict__ kl,
                               __half* __restrict__ vh,
                               __half* __restrict__ vl) {
  const int i = blockIdx.x * blockDim.x + threadIdx.x;
  if (i >= kT * 1024 / 4) return;
  const int e = i * 4;
  const int t = e >> 10;
  const int rem = e & 1023;
  const int kv = rem >> 7, d = rem & 127;
  const size_t o = ((size_t)kv * kT + t) * kHD + d;
  const float4 kf = *(const float4*)(qkv + (size_t)t * kQKV + kKOff + rem);
  const float4 vf = *(const float4*)(qkv + (size_t)t * kQKV + kVOff + rem);
  uint32_t l0, l1;
  uint32_t h0 = packsplit(kf.x, kf.y, l0);
  uint32_t h1 = packsplit(kf.z, kf.w, l1);
  *(uint2*)(kh + o) = make_uint2(h0, h1);
  *(uint2*)(kl + o) = make_uint2(l0, l1);
  h0 = packsplit_h(vf.x, vf.y, l0);
  h1 = packsplit_h(vf.z, vf.w, l1);
  *(uint2*)(vh + o) = make_uint2(h0, h1);
  *(uint2*)(vl + o) = make_uint2(l0, l1);
}

// =====================================================================
// bf16x3 GEMM on mma.sync, cp.async 2-stage pipeline (unchanged, proven).
// =====================================================================
constexpr int kLds = 40;
constexpr int kGTileB = 128 * kLds * 2;
constexpr int kGStageB = 4 * kGTileB;
constexpr int kGemmSmem = 2 * kGStageB;  // 81920 B

__global__ __launch_bounds__(256)
void gemm_mma_kernel(const __nv_bfloat16* __restrict__ Ah,
                     const __nv_bfloat16* __restrict__ Al,
                     const __nv_bfloat16* __restrict__ Bh,
                     const __nv_bfloat16* __restrict__ Bl,
                     float* __restrict__ C, int NT) {
  constexpr int K = kH;
  constexpr int BK = 32;
  constexpr int NST = K / BK;
  extern __shared__ __align__(16) __nv_bfloat16 gsm[];
  const uint32_t base = smem_u32(gsm);

  const int tid = threadIdx.x;
  const int wid = tid >> 5, lane = tid & 31;
  const int m0 = blockIdx.y << 7;
  const int n0 = blockIdx.x << 7;
  const int wm = (wid >> 2) << 6;
  const int wn = (wid & 3) << 5;

  const int lr = tid >> 2, ls = tid & 3;
  const uint32_t so0 = (uint32_t)(lr * 80 + ls * 16);
  const uint32_t so1 = (uint32_t)((lr + 64) * 80 + ls * 16);

  float acc[4][4][4];
#pragma unroll
  for (int i = 0; i < 4; ++i)
#pragma unroll
    for (int j = 0; j < 4; ++j)
#pragma unroll
      for (int q = 0; q < 4; ++q) acc[i][j][q] = 0.f;

  const size_t aOff0 = (size_t)(m0 + lr) * K + ls * 8;
  const size_t aOff1 = aOff0 + (size_t)64 * K;
  const size_t bOff0 = (size_t)(n0 + lr) * K + ls * 8;
  const size_t bOff1 = bOff0 + (size_t)64 * K;

#define GLOAD(st, kc) do {                                        \
    const uint32_t sb = base + (uint32_t)((st) * kGStageB);      \
    cp16(sb + so0,                Ah + aOff0 + (kc));            \
    cp16(sb + so1,                Ah + aOff1 + (kc));            \
    cp16(sb + kGTileB + so0,      Al + aOff0 + (kc));            \
    cp16(sb + kGTileB + so1,      Al + aOff1 + (kc));            \
    cp16(sb + 2 * kGTileB + so0,  Bh + bOff0 + (kc));            \
    cp16(sb + 2 * kGTileB + so1,  Bh + bOff1 + (kc));            \
    cp16(sb + 3 * kGTileB + so0,  Bl + bOff0 + (kc));            \
    cp16(sb + 3 * kGTileB + so1,  Bl + bOff1 + (kc));            \
  } while (0)

  GLOAD(0, 0);
  CP_COMMIT();
  GLOAD(1, BK);
  CP_COMMIT();

#pragma unroll 1
  for (int kt = 0; kt < NST; ++kt) {
    if (kt < NST - 2) CP_WAIT1(); else CP_WAIT0();
    __syncthreads();

    const uint32_t sb = base + (uint32_t)((kt & 1) * kGStageB);
#pragma unroll
    for (int kh = 0; kh < 2; ++kh) {
      const int slot = kh * 2 + (lane >> 4);
      const int arow = wm + (lane & 15);
      const int brow = wn + (lane & 15);

      uint32_t ah[4][4], al[4][4];
#pragma unroll
      for (int i = 0; i < 4; ++i) {
        const uint32_t ad = sb + (uint32_t)((arow + 16 * i) * 80 + slot * 16);
        ldsm4(ah[i], ad);
        ldsm4(al[i], ad + kGTileB);
      }
      uint32_t bh[2][4], bl[2][4];
#pragma unroll
      for (int p = 0; p < 2; ++p) {
        const uint32_t bd = sb + (uint32_t)(2 * kGTileB) +
                            (uint32_t)((brow + 16 * p) * 80 + slot * 16);
        ldsm4(bh[p], bd);
        ldsm4(bl[p], bd + kGTileB);
      }
#pragma unroll
      for (int i = 0; i < 4; ++i)
#pragma unroll
        for (int j = 0; j < 4; ++j) {
          const int p = j >> 1, w = j & 1;
          mma_bf16(acc[i][j], ah[i], bh[p][w], bh[p][2 + w]);
          mma_bf16(acc[i][j], ah[i], bl[p][w], bl[p][2 + w]);
          mma_bf16(acc[i][j], al[i], bh[p][w], bh[p][2 + w]);
        }
    }
    __syncthreads();
    if (kt + 2 < NST) {
      GLOAD(kt & 1, (kt + 2) * BK);
      CP_COMMIT();
    }
  }
#undef GLOAD

  const int g = lane >> 2, t4 = lane & 3;
#pragma unroll
  for (int i = 0; i < 4; ++i) {
    const int r0 = m0 + wm + 16 * i + g;
#pragma unroll
    for (int j = 0; j < 4; ++j) {
      const int col = n0 + wn + 8 * j + 2 * t4;
      *(float2*)(C + (size_t)r0 * NT + col) =
          make_float2(acc[i][j][0], acc[i][j][1]);
      *(float2*)(C + (size_t)(r0 + 8) * NT + col) =
          make_float2(acc[i][j][2], acc[i][j][3]);
    }
  }
}

// =====================================================================
// RoPE in place (fp32 exp2f inv_freq)
// =====================================================================
__global__ void rope_kernel(const int* __restrict__ pos) {
  const int idx = blockIdx.x * blockDim.x + threadIdx.x;
  const int totq = kT * kNH * 64;
  const int tot = totq + kT * kNKV * 64;
  if (idx >= tot) return;

  float* base;
  int t, i;
  if (idx < totq) {
    t = idx / (kNH * 64);
    const int r = idx - t * (kNH * 64);
    i = r & 63;
    base = g_qkv + (size_t)t * kQKV + (r >> 6) * kHD;
  } else {
    const int j = idx - totq;
    t = j / (kNKV * 64);
    const int r = j - t * (kNKV * 64);
    i = r & 63;
    base = g_qkv + (size_t)t * kQKV + kKOff + (r >> 6) * kHD;
  }
  constexpr float kNegLog2Theta64 = -0.29580667120644826f;
  const float inv = exp2f((float)i * kNegLog2Theta64);
  const float f = (float)pos[t] * inv;
  float sn, cs;
  sincosf(f, &sn, &cs);
  const float x1 = base[i], x2 = base[i + 64];
  base[i] = x1 * cs - x2 * sn;
  base[i + 64] = x2 * cs + x1 * sn;
}

// =====================================================================
// Flash attention on mma.sync. S: bf16x3 (Q/K), PV: fp16 P (single) x
// fp16 V hi/lo (2 terms). exp2-domain softmax (log2e folded into Q).
// Q fragments hoisted out of the kv loop.
// =====================================================================
constexpr int kAPad  = 136;
constexpr int kATile = 64 * kAPad;
constexpr uint32_t kTileB = kATile * 2;

__global__ __launch_bounds__(128, 2)
void attn_mma_kernel(const __nv_bfloat16* __restrict__ qh,
                     const __nv_bfloat16* __restrict__ ql,
                     const __nv_bfloat16* __restrict__ kh,
                     const __nv_bfloat16* __restrict__ kl,
                     const __half* __restrict__ vh,
                     const __half* __restrict__ vl,
                     __nv_bfloat16* __restrict__ oh,
                     __nv_bfloat16* __restrict__ ol) {
  extern __shared__ __nv_bfloat16 sma[];
  const int h = blockIdx.x;
  const int qb = (int)gridDim.y - 1 - (int)blockIdx.y;
  const int kvi = h >> 2;
  const int tid = threadIdx.x;
  const int wid = tid >> 5, lane = tid & 31;
  const int q0 = qb << 6;
  const uint32_t base = smem_u32(sma);
  const int g = lane >> 2, t4 = lane & 3;

  // ---- load Q tiles ----
  {
    const __nv_bfloat16* Qh = qh + ((size_t)h * kT + q0) * kHD;
    const __nv_bfloat16* Ql = ql + ((size_t)h * kT + q0) * kHD;
#pragma unroll
    for (int j = 0; j < 8; ++j) {
      const int idx = tid + (j << 7);
      const int r = idx >> 4, s = idx & 15;
      const int so = r * kAPad + s * 8;
      *(uint4*)(sma + so)          = *(const uint4*)(Qh + r * 128 + s * 8);
      *(uint4*)(sma + kATile + so) = *(const uint4*)(Ql + r * 128 + s * 8);
    }
  }
  __syncthreads();

  const uint32_t aAddr =
      base + 2u * (uint32_t)(((wid << 4) + (lane & 15)) * kAPad + ((lane >> 4) << 3));
  const uint32_t kAddr =
      base + 2u * kTileB +
      2u * (uint32_t)((lane & 15) * kAPad + ((lane >> 4) << 3));
  const uint32_t vAddr =
      base + 4u * kTileB +
      2u * (uint32_t)((lane & 15) * kAPad + ((lane >> 4) << 3));

  // ---- hoist Q fragments (loop-invariant) ----
  uint32_t qfh[8][4], qfl[8][4];
#pragma unroll
  for (int kc = 0; kc < 8; ++kc) {
    ldsm4(qfh[kc], aAddr + kc * 32);
    ldsm4(qfl[kc], aAddr + kc * 32 + kTileB);
  }

  float o[16][4];
#pragma unroll
  for (int t = 0; t < 16; ++t)
#pragma unroll
    for (int q = 0; q < 4; ++q) o[t][q] = 0.f;
  float mrun0 = -1e30f, mrun1 = -1e30f, lrun0 = 0.f, lrun1 = 0.f;

#pragma unroll 1
  for (int kb = 0; kb <= qb; ++kb) {
    __syncthreads();
    const size_t kvoff = ((size_t)kvi * kT + ((size_t)kb << 6)) * kHD;
#pragma unroll
    for (int j = 0; j < 8; ++j) {
      const int idx = tid + (j << 7);
      const int r = idx >> 4, s = idx & 15;
      const uint32_t so = (uint32_t)((r * kAPad + s * 8) * 2);
      const size_t go = kvoff + r * 128 + s * 8;
      cp16(base + 2u * kTileB + so, kh + go);
      cp16(base + 3u * kTileB + so, kl + go);
      cp16(base + 4u * kTileB + so, vh + go);
      cp16(base + 5u * kTileB + so, vl + go);
    }
    CP_COMMIT();
    CP_WAIT0();
    __syncthreads();

    // ---- S = Q K^T (bf16x3) ----
    float sacc[8][4];
#pragma unroll
    for (int j = 0; j < 8; ++j)
#pragma unroll
      for (int q = 0; q < 4; ++q) sacc[j][q] = 0.f;

#pragma unroll
    for (int kc = 0; kc < 8; ++kc) {
#pragma unroll
      for (int p = 0; p < 4; ++p) {
        uint32_t bk[4], bkl_[4];
        const uint32_t bd = kAddr + (uint32_t)(p * 16 * kAPad * 2) + kc * 32;
        ldsm4(bk, bd);
        ldsm4(bkl_, bd + kTileB);
#pragma unroll
        for (int w2 = 0; w2 < 2; ++w2) {
          const int j = p * 2 + w2;
          mma_bf16(sacc[j], qfh[kc], bk[w2], bk[2 + w2]);
          mma_bf16(sacc[j], qfh[kc], bkl_[w2], bkl_[2 + w2]);
          mma_bf16(sacc[j], qfl[kc], bk[w2], bk[2 + w2]);
        }
      }
    }

    if (kb == qb) {
      const int r0 = (wid << 4) + g;
#pragma unroll
      for (int j = 0; j < 8; ++j) {
        const int c = (j << 3) + (t4 << 1);
        if (c > r0)         sacc[j][0] = -1e30f;
        if (c + 1 > r0)     sacc[j][1] = -1e30f;
        if (c > r0 + 8)     sacc[j][2] = -1e30f;
        if (c + 1 > r0 + 8) sacc[j][3] = -1e30f;
      }
    }

    // ---- online softmax in exp2 domain ----
    float mx0 = -1e30f, mx1 = -1e30f;
#pragma unroll
    for (int j = 0; j < 8; ++j) {
      mx0 = fmaxf(mx0, fmaxf(sacc[j][0], sacc[j][1]));
      mx1 = fmaxf(mx1, fmaxf(sacc[j][2], sacc[j][3]));
    }
    mx0 = fmaxf(mx0, __shfl_xor_sync(0xffffffffu, mx0, 1));
    mx0 = fmaxf(mx0, __shfl_xor_sync(0xffffffffu, mx0, 2));
    mx1 = fmaxf(mx1, __shfl_xor_sync(0xffffffffu, mx1, 1));
    mx1 = fmaxf(mx1, __shfl_xor_sync(0xffffffffu, mx1, 2));
    const float mn0 = fmaxf(mrun0, mx0), mn1 = fmaxf(mrun1, mx1);
    const float f0 = exp2f(mrun0 - mn0), f1 = exp2f(mrun1 - mn1);
    float rs0 = 0.f, rs1 = 0.f;
#pragma unroll
    for (int j = 0; j < 8; ++j) {
      sacc[j][0] = exp2f(sacc[j][0] - mn0);
      sacc[j][1] = exp2f(sacc[j][1] - mn0);
      sacc[j][2] = exp2f(sacc[j][2] - mn1);
      sacc[j][3] = exp2f(sacc[j][3] - mn1);
      rs0 += sacc[j][0] + sacc[j][1];
      rs1 += sacc[j][2] + sacc[j][3];
    }
    rs0 += __shfl_xor_sync(0xffffffffu, rs0, 1);
    rs0 += __shfl_xor_sync(0xffffffffu, rs0, 2);
    rs1 += __shfl_xor_sync(0xffffffffu, rs1, 1);
    rs1 += __shfl_xor_sync(0xffffffffu, rs1, 2);
    lrun0 = lrun0 * f0 + rs0;
    lrun1 = lrun1 * f1 + rs1;
    mrun0 = mn0;
    mrun1 = mn1;
#pragma unroll
    for (int t = 0; t < 16; ++t) {
      o[t][0] *= f0; o[t][1] *= f0; o[t][2] *= f1; o[t][3] *= f1;
    }

    // ---- P fragments: fp16, single term ----
    uint32_t pha[4][4];
#pragma unroll
    for (int jj = 0; jj < 4; ++jj) {
      pha[jj][0] = packh2(sacc[2 * jj][0], sacc[2 * jj][1]);
      pha[jj][1] = packh2(sacc[2 * jj][2], sacc[2 * jj][3]);
      pha[jj][2] = packh2(sacc[2 * jj + 1][0], sacc[2 * jj + 1][1]);
      pha[jj][3] = packh2(sacc[2 * jj + 1][2], sacc[2 * jj + 1][3]);
    }

    // ---- O += P V (fp16: P single x V hi/lo) ----
#pragma unroll
    for (int dc = 0; dc < 8; ++dc) {
#pragma unroll
      for (int jj = 0; jj < 4; ++jj) {
        uint32_t bv[4], bvl_[4];
        const uint32_t vd = vAddr + (uint32_t)(jj * 16 * kAPad * 2) + dc * 32;
        ldsm4t(bv, vd);
        ldsm4t(bvl_, vd + kTileB);
        mma_fp16(o[2 * dc], pha[jj], bv[0], bv[1]);
        mma_fp16(o[2 * dc], pha[jj], bvl_[0], bvl_[1]);
        mma_fp16(o[2 * dc + 1], pha[jj], bv[2], bv[3]);
        mma_fp16(o[2 * dc + 1], pha[jj], bvl_[2], bvl_[3]);
      }
    }
  }

  // ---- epilogue: normalize; write bf16 hi/lo as GEMM2's A ----
  const float i0 = 1.f / lrun0, i1 = 1.f / lrun1;
  const int row0 = q0 + (wid << 4) + g;
#pragma unroll
  for (int t = 0; t < 16; ++t) {
    const int d = (h << 7) + (t << 3) + (t4 << 1);
    uint32_t lo;
    uint32_t hi = packsplit(o[t][0] * i0, o[t][1] * i0, lo);
    *(uint32_t*)(oh + (size_t)row0 * kQS + d) = hi;
    *(uint32_t*)(ol + (size_t)row0 * kQS + d) = lo;
    hi = packsplit(o[t][2] * i1, o[t][3] * i1, lo);
    *(uint32_t*)(oh + (size_t)(row0 + 8) * kQS + d) = hi;
    *(uint32_t*)(ol + (size_t)(row0 + 8) * kQS + d) = lo;
  }
}

// =====================================================================
// launch
// =====================================================================
extern "C" void kernel_launch(void* const* d_in, const int* in_sizes, int n_in,
                              void* d_out, int out_size) {
  const int*   positions = (const int*)d_in[0];
  const float* hidden    = (const float*)d_in[1];
  const float* wqkv      = (const float*)d_in[2];
  const float* wo        = (const float*)d_in[3];
  float*       out       = (float*)d_out;

  void *p_qkv, *p_ah, *p_al, *p_b1h, *p_b1l, *p_b2h, *p_b2l;
  void *p_qh, *p_ql, *p_kh, *p_kl, *p_vh, *p_vl;
  cudaGetSymbolAddress(&p_qkv, g_qkv);
  cudaGetSymbolAddress(&p_ah, g_ah);
  cudaGetSymbolAddress(&p_al, g_al);
  cudaGetSymbolAddress(&p_b1h, g_b1h);
  cudaGetSymbolAddress(&p_b1l, g_b1l);
  cudaGetSymbolAddress(&p_b2h, g_b2h);
  cudaGetSymbolAddress(&p_b2l, g_b2l);
  cudaGetSymbolAddress(&p_qh, g_qh);
  cudaGetSymbolAddress(&p_ql, g_ql);
  cudaGetSymbolAddress(&p_kh, g_kh);
  cudaGetSymbolAddress(&p_kl, g_kl);
  cudaGetSymbolAddress(&p_vh, g_vh);
  cudaGetSymbolAddress(&p_vl, g_vl);

  float* qkv = (float*)p_qkv;
  __nv_bfloat16* ah = (__nv_bfloat16*)p_ah;
  __nv_bfloat16* al = (__nv_bfloat16*)p_al;
  __nv_bfloat16* b1h = (__nv_bfloat16*)p_b1h;
  __nv_bfloat16* b1l = (__nv_bfloat16*)p_b1l;
  __nv_bfloat16* b2h = (__nv_bfloat16*)p_b2h;
  __nv_bfloat16* b2l = (__nv_bfloat16*)p_b2l;
  __nv_bfloat16* qh = (__nv_bfloat16*)p_qh;
  __nv_bfloat16* ql = (__nv_bfloat16*)p_ql;
  __nv_bfloat16* kh = (__nv_bfloat16*)p_kh;
  __nv_bfloat16* kl = (__nv_bfloat16*)p_kl;
  __half* vh = (__half*)p_vh;
  __half* vl = (__half*)p_vl;

  constexpr int kAttnSmem = 6 * kATile * 2;  // 104448 B
  cudaFuncSetAttribute(attn_mma_kernel,
                       cudaFuncAttributeMaxDynamicSharedMemorySize, kAttnSmem);
  cudaFuncSetAttribute(gemm_mma_kernel,
                       cudaFuncAttributeMaxDynamicSharedMemorySize, kGemmSmem);

  // QKV projection
  split_kernel<<<kT * kH / 4 / 256, 256>>>(hidden, ah, al, kT * kH / 4);
  transpose_split_kernel<<<dim3(kQKV / 32, kH / 32), dim3(32, 8)>>>(
      wqkv, b1h, b1l, kH, kQKV);
  gemm_mma_kernel<<<dim3(kQKV / 128, kT / 128), 256, kGemmSmem>>>(
      ah, al, b1h, b1l, qkv, kQKV);

  // RoPE, then split q/k/v into attention layouts
  const int ropeTot = kT * (kNH + kNKV) * 64;
  rope_kernel<<<(ropeTot + 255) / 256, 256>>>(positions);
  qsplit_kernel<<<kT * kQS / 4 / 256, 256>>>(qkv, qh, ql);
  kvsplit_kernel<<<kT * 1024 / 4 / 256, 256>>>(qkv, kh, kl, vh, vl);

  // Attention (writes GEMM2's A hi/lo directly)
  attn_mma_kernel<<<dim3(kNH, kT / 64), 128, kAttnSmem>>>(
      qh, ql, kh, kl, vh, vl, ah, al);

  // Output projection
  transpose_split_kernel<<<dim3(kQS / 32, kH / 32), dim3(32, 8)>>>(
      wo, b2h, b2l, kH, kQS);
  gemm_mma_kernel<<<dim3(kQS / 128, kT / 128), 256, kGemmSmem>>>(
      ah, al, b2h, b2l, out, kQS);
}

// round 11
// speedup vs baseline: 2.8601x; 1.0076x over previous
#include <cuda_runtime.h>
#include <cuda_bf16.h>
#include <cuda_fp16.h>
#include <math.h>
#include <stdint.h>

// ----------------- problem constants -----------------
constexpr int kT    = 2048;
constexpr int kH    = 4096;
constexpr int kNH   = 32;
constexpr int kNKV  = 8;
constexpr int kHD   = 128;
constexpr int kQKV  = 6144;
constexpr int kQS   = 4096;
constexpr int kKOff = 4096;
constexpr int kVOff = 5120;

// ----------------- scratch (no allocations allowed) -----------------
__device__ float g_qkv[kT * kQKV];
__device__ __align__(16) __nv_bfloat16 g_ah[kT * kH];     // GEMM A hi
__device__ __align__(16) __nv_bfloat16 g_al[kT * kH];     // GEMM A lo
__device__ __align__(16) __nv_bfloat16 g_b1h[kQKV * kH];  // w_qkv^T hi [N,K]
__device__ __align__(16) __nv_bfloat16 g_b1l[kQKV * kH];
__device__ __align__(16) __nv_bfloat16 g_b2h[kQS * kH];   // w_o^T hi [N,K]
__device__ __align__(16) __nv_bfloat16 g_b2l[kQS * kH];
__device__ __align__(16) __nv_bfloat16 g_qh[kNH * kT * kHD];   // q scaled hi [h][t][d]
__device__ __align__(16) __nv_bfloat16 g_ql[kNH * kT * kHD];
__device__ __align__(16) __nv_bfloat16 g_kh[kNKV * kT * kHD];  // k hi [kv][t][d]
__device__ __align__(16) __nv_bfloat16 g_kl[kNKV * kT * kHD];
__device__ __align__(16) __half       g_vh[kNKV * kT * kHD];   // v fp16 hi
__device__ __align__(16) __half       g_vl[kNKV * kT * kHD];   // v fp16 lo

// ================= low-level helpers =================
__device__ __forceinline__ uint32_t smem_u32(const void* p) {
  uint32_t a;
  asm("{ .reg .u64 t; cvta.to.shared.u64 t, %1; cvt.u32.u64 %0, t; }"
      : "=r"(a) : "l"(p));
  return a;
}
__device__ __forceinline__ void cp16(uint32_t saddr, const void* g) {
  asm volatile("cp.async.cg.shared.global [%0], [%1], 16;"
               :: "r"(saddr), "l"(g));
}
#define CP_COMMIT() asm volatile("cp.async.commit_group;" ::: "memory")
#define CP_WAIT1()  asm volatile("cp.async.wait_group 1;" ::: "memory")
#define CP_WAIT0()  asm volatile("cp.async.wait_group 0;" ::: "memory")

__device__ __forceinline__ void ldsm4(uint32_t* r, uint32_t addr) {
  asm volatile("ldmatrix.sync.aligned.m8n8.x4.shared.b16 {%0,%1,%2,%3}, [%4];"
               : "=r"(r[0]), "=r"(r[1]), "=r"(r[2]), "=r"(r[3]) : "r"(addr));
}
__device__ __forceinline__ void ldsm4t(uint32_t* r, uint32_t addr) {
  asm volatile("ldmatrix.sync.aligned.m8n8.x4.trans.shared.b16 {%0,%1,%2,%3}, [%4];"
               : "=r"(r[0]), "=r"(r[1]), "=r"(r[2]), "=r"(r[3]) : "r"(addr));
}
__device__ __forceinline__ void mma_bf16(float* c, const uint32_t* a,
                                         uint32_t b0, uint32_t b1) {
  asm volatile(
      "mma.sync.aligned.m16n8k16.row.col.f32.bf16.bf16.f32 "
      "{%0,%1,%2,%3}, {%4,%5,%6,%7}, {%8,%9}, {%0,%1,%2,%3};"
      : "+f"(c[0]), "+f"(c[1]), "+f"(c[2]), "+f"(c[3])
      : "r"(a[0]), "r"(a[1]), "r"(a[2]), "r"(a[3]), "r"(b0), "r"(b1));
}
__device__ __forceinline__ void mma_fp16(float* c, const uint32_t* a,
                                         uint32_t b0, uint32_t b1) {
  asm volatile(
      "mma.sync.aligned.m16n8k16.row.col.f32.f16.f16.f32 "
      "{%0,%1,%2,%3}, {%4,%5,%6,%7}, {%8,%9}, {%0,%1,%2,%3};"
      : "+f"(c[0]), "+f"(c[1]), "+f"(c[2]), "+f"(c[3])
      : "r"(a[0]), "r"(a[1]), "r"(a[2]), "r"(a[3]), "r"(b0), "r"(b1));
}
__device__ __forceinline__ uint32_t packsplit(float x, float y, uint32_t& lo) {
  __nv_bfloat16 hx = __float2bfloat16_rn(x);
  __nv_bfloat16 hy = __float2bfloat16_rn(y);
  __nv_bfloat162 hp(hx, hy);
  __nv_bfloat162 lp(__float2bfloat16_rn(x - __bfloat162float(hx)),
                    __float2bfloat16_rn(y - __bfloat162float(hy)));
  lo = *(uint32_t*)&lp;
  return *(uint32_t*)&hp;
}
__device__ __forceinline__ uint32_t packsplit_h(float x, float y, uint32_t& lo) {
  __half hx = __float2half_rn(x), hy = __float2half_rn(y);
  __half2 hp(hx, hy);
  __half2 lp(__float2half_rn(x - __half2float(hx)),
             __float2half_rn(y - __half2float(hy)));
  lo = *(uint32_t*)&lp;
  return *(uint32_t*)&hp;
}
__device__ __forceinline__ uint32_t packh2(float x, float y) {
  __half2 h = __floats2half2_rn(x, y);
  return *(uint32_t*)&h;
}

// =====================================================================
// Conversion kernels
// =====================================================================
__global__ void split_kernel(const float* __restrict__ X,
                             __nv_bfloat16* __restrict__ H,
                             __nv_bfloat16* __restrict__ L, int total4) {
  const int i = blockIdx.x * blockDim.x + threadIdx.x;
  if (i >= total4) return;
  const float4 v = ((const float4*)X)[i];
  uint32_t l0, l1;
  const uint32_t h0 = packsplit(v.x, v.y, l0);
  const uint32_t h1 = packsplit(v.z, v.w, l1);
  ((uint2*)H)[i] = make_uint2(h0, h1);
  ((uint2*)L)[i] = make_uint2(l0, l1);
}

__global__ void transpose_split_kernel(const float* __restrict__ W,
                                       __nv_bfloat16* __restrict__ Th,
                                       __nv_bfloat16* __restrict__ Tl,
                                       int K, int N) {
  __shared__ float t[32][33];
  const int n0 = blockIdx.x * 32, k0 = blockIdx.y * 32;
  const int tx = threadIdx.x, ty = threadIdx.y;
#pragma unroll
  for (int j = 0; j < 4; ++j)
    t[ty + 8 * j][tx] = W[(size_t)(k0 + ty + 8 * j) * N + n0 + tx];
  __syncthreads();
#pragma unroll
  for (int j = 0; j < 4; ++j) {
    const int n = ty + 8 * j;
    const float v = t[tx][n];
    const __nv_bfloat16 h = __float2bfloat16_rn(v);
    const size_t o = (size_t)(n0 + n) * K + k0 + tx;
    Th[o] = h;
    Tl[o] = __float2bfloat16_rn(v - __bfloat162float(h));
  }
}

// RoPE fused with q/k bf16 hi/lo splitting. Reads fp32 qkv, writes rotated
// values straight into the attention layouts (q pre-scaled by 1/sqrt(HD)*log2e).
__global__ void rope_split_kernel(const int* __restrict__ pos,
                                  const float* __restrict__ qkv,
                                  __nv_bfloat16* __restrict__ qh,
                                  __nv_bfloat16* __restrict__ ql,
                                  __nv_bfloat16* __restrict__ kh,
                                  __nv_bfloat16* __restrict__ kl) {
  const int idx = blockIdx.x * blockDim.x + threadIdx.x;
  const int totq = kT * kNH * 64;
  const int tot = totq + kT * kNKV * 64;
  if (idx >= tot) return;

  const float* src;
  __nv_bfloat16 *dh, *dl;
  int t, i;
  float scale;
  size_t o;
  if (idx < totq) {
    t = idx / (kNH * 64);
    const int r = idx - t * (kNH * 64);
    const int hh = r >> 6;
    i = r & 63;
    src = qkv + (size_t)t * kQKV + hh * kHD;
    o = ((size_t)hh * kT + t) * kHD;
    dh = qh; dl = ql;
    scale = 0.08838834764831845f * 1.4426950408889634f;  // 1/sqrt(128)*log2e
  } else {
    const int j = idx - totq;
    t = j / (kNKV * 64);
    const int r = j - t * (kNKV * 64);
    const int kv = r >> 6;
    i = r & 63;
    src = qkv + (size_t)t * kQKV + kKOff + kv * kHD;
    o = ((size_t)kv * kT + t) * kHD;
    dh = kh; dl = kl;
    scale = 1.0f;
  }
  constexpr float kNegLog2Theta64 = -0.29580667120644826f;
  const float inv = exp2f((float)i * kNegLog2Theta64);
  const float f = (float)pos[t] * inv;
  float sn, cs;
  sincosf(f, &sn, &cs);
  const float x1 = src[i], x2 = src[i + 64];
  const float y1 = (x1 * cs - x2 * sn) * scale;
  const float y2 = (x2 * cs + x1 * sn) * scale;
  const __nv_bfloat16 h1 = __float2bfloat16_rn(y1);
  const __nv_bfloat16 h2 = __float2bfloat16_rn(y2);
  dh[o + i]      = h1;
  dl[o + i]      = __float2bfloat16_rn(y1 - __bfloat162float(h1));
  dh[o + i + 64] = h2;
  dl[o + i + 64] = __float2bfloat16_rn(y2 - __bfloat162float(h2));
}

// v region of g_qkv -> fp16 hi/lo, layout [kv][t][d]
__global__ void vsplit_kernel(const float* __restrict__ qkv,
                              __half* __restrict__ vh,
                              __half* __restrict__ vl) {
  const int i = blockIdx.x * blockDim.x + threadIdx.x;
  if (i >= kT * 1024 / 4) return;
  const int e = i * 4;
  const int t = e >> 10;
  const int rem = e & 1023;
  const int kv = rem >> 7, d = rem & 127;
  const size_t o = ((size_t)kv * kT + t) * kHD + d;
  const float4 vf = *(const float4*)(qkv + (size_t)t * kQKV + kVOff + rem);
  uint32_t l0, l1;
  const uint32_t h0 = packsplit_h(vf.x, vf.y, l0);
  const uint32_t h1 = packsplit_h(vf.z, vf.w, l1);
  *(uint2*)(vh + o) = make_uint2(h0, h1);
  *(uint2*)(vl + o) = make_uint2(l0, l1);
}

// =====================================================================
// bf16x3 GEMM on mma.sync, cp.async 2-stage pipeline (unchanged, proven).
// =====================================================================
constexpr int kLds = 40;
constexpr int kGTileB = 128 * kLds * 2;
constexpr int kGStageB = 4 * kGTileB;
constexpr int kGemmSmem = 2 * kGStageB;  // 81920 B

__global__ __launch_bounds__(256)
void gemm_mma_kernel(const __nv_bfloat16* __restrict__ Ah,
                     const __nv_bfloat16* __restrict__ Al,
                     const __nv_bfloat16* __restrict__ Bh,
                     const __nv_bfloat16* __restrict__ Bl,
                     float* __restrict__ C, int NT) {
  constexpr int K = kH;
  constexpr int BK = 32;
  constexpr int NST = K / BK;
  extern __shared__ __align__(16) __nv_bfloat16 gsm[];
  const uint32_t base = smem_u32(gsm);

  const int tid = threadIdx.x;
  const int wid = tid >> 5, lane = tid & 31;
  const int m0 = blockIdx.y << 7;
  const int n0 = blockIdx.x << 7;
  const int wm = (wid >> 2) << 6;
  const int wn = (wid & 3) << 5;

  const int lr = tid >> 2, ls = tid & 3;
  const uint32_t so0 = (uint32_t)(lr * 80 + ls * 16);
  const uint32_t so1 = (uint32_t)((lr + 64) * 80 + ls * 16);

  float acc[4][4][4];
#pragma unroll
  for (int i = 0; i < 4; ++i)
#pragma unroll
    for (int j = 0; j < 4; ++j)
#pragma unroll
      for (int q = 0; q < 4; ++q) acc[i][j][q] = 0.f;

  const size_t aOff0 = (size_t)(m0 + lr) * K + ls * 8;
  const size_t aOff1 = aOff0 + (size_t)64 * K;
  const size_t bOff0 = (size_t)(n0 + lr) * K + ls * 8;
  const size_t bOff1 = bOff0 + (size_t)64 * K;

#define GLOAD(st, kc) do {                                        \
    const uint32_t sb = base + (uint32_t)((st) * kGStageB);      \
    cp16(sb + so0,                Ah + aOff0 + (kc));            \
    cp16(sb + so1,                Ah + aOff1 + (kc));            \
    cp16(sb + kGTileB + so0,      Al + aOff0 + (kc));            \
    cp16(sb + kGTileB + so1,      Al + aOff1 + (kc));            \
    cp16(sb + 2 * kGTileB + so0,  Bh + bOff0 + (kc));            \
    cp16(sb + 2 * kGTileB + so1,  Bh + bOff1 + (kc));            \
    cp16(sb + 3 * kGTileB + so0,  Bl + bOff0 + (kc));            \
    cp16(sb + 3 * kGTileB + so1,  Bl + bOff1 + (kc));            \
  } while (0)

  GLOAD(0, 0);
  CP_COMMIT();
  GLOAD(1, BK);
  CP_COMMIT();

#pragma unroll 1
  for (int kt = 0; kt < NST; ++kt) {
    if (kt < NST - 2) CP_WAIT1(); else CP_WAIT0();
    __syncthreads();

    const uint32_t sb = base + (uint32_t)((kt & 1) * kGStageB);
#pragma unroll
    for (int kh = 0; kh < 2; ++kh) {
      const int slot = kh * 2 + (lane >> 4);
      const int arow = wm + (lane & 15);
      const int brow = wn + (lane & 15);

      uint32_t ah[4][4], al[4][4];
#pragma unroll
      for (int i = 0; i < 4; ++i) {
        const uint32_t ad = sb + (uint32_t)((arow + 16 * i) * 80 + slot * 16);
        ldsm4(ah[i], ad);
        ldsm4(al[i], ad + kGTileB);
      }
      uint32_t bh[2][4], bl[2][4];
#pragma unroll
      for (int p = 0; p < 2; ++p) {
        const uint32_t bd = sb + (uint32_t)(2 * kGTileB) +
                            (uint32_t)((brow + 16 * p) * 80 + slot * 16);
        ldsm4(bh[p], bd);
        ldsm4(bl[p], bd + kGTileB);
      }
#pragma unroll
      for (int i = 0; i < 4; ++i)
#pragma unroll
        for (int j = 0; j < 4; ++j) {
          const int p = j >> 1, w = j & 1;
          mma_bf16(acc[i][j], ah[i], bh[p][w], bh[p][2 + w]);
          mma_bf16(acc[i][j], ah[i], bl[p][w], bl[p][2 + w]);
          mma_bf16(acc[i][j], al[i], bh[p][w], bh[p][2 + w]);
        }
    }
    __syncthreads();
    if (kt + 2 < NST) {
      GLOAD(kt & 1, (kt + 2) * BK);
      CP_COMMIT();
    }
  }
#undef GLOAD

  const int g = lane >> 2, t4 = lane & 3;
#pragma unroll
  for (int i = 0; i < 4; ++i) {
    const int r0 = m0 + wm + 16 * i + g;
#pragma unroll
    for (int j = 0; j < 4; ++j) {
      const int col = n0 + wn + 8 * j + 2 * t4;
      *(float2*)(C + (size_t)r0 * NT + col) =
          make_float2(acc[i][j][0], acc[i][j][1]);
      *(float2*)(C + (size_t)(r0 + 8) * NT + col) =
          make_float2(acc[i][j][2], acc[i][j][3]);
    }
  }
}

// =====================================================================
// Flash attention on mma.sync. S: bf16x3, PV: fp16 P x fp16 V hi/lo.
// K and V committed as separate cp.async groups: V load overlaps S+softmax.
// =====================================================================
constexpr int kAPad  = 136;
constexpr int kATile = 64 * kAPad;
constexpr uint32_t kTileB = kATile * 2;

__global__ __launch_bounds__(128, 2)
void attn_mma_kernel(const __nv_bfloat16* __restrict__ qh,
                     const __nv_bfloat16* __restrict__ ql,
                     const __nv_bfloat16* __restrict__ kh,
                     const __nv_bfloat16* __restrict__ kl,
                     const __half* __restrict__ vh,
                     const __half* __restrict__ vl,
                     __nv_bfloat16* __restrict__ oh,
                     __nv_bfloat16* __restrict__ ol) {
  extern __shared__ __nv_bfloat16 sma[];
  const int h = blockIdx.x;
  const int qb = (int)gridDim.y - 1 - (int)blockIdx.y;
  const int kvi = h >> 2;
  const int tid = threadIdx.x;
  const int wid = tid >> 5, lane = tid & 31;
  const int q0 = qb << 6;
  const uint32_t base = smem_u32(sma);
  const int g = lane >> 2, t4 = lane & 3;

  // ---- load Q tiles ----
  {
    const __nv_bfloat16* Qh = qh + ((size_t)h * kT + q0) * kHD;
    const __nv_bfloat16* Ql = ql + ((size_t)h * kT + q0) * kHD;
#pragma unroll
    for (int j = 0; j < 8; ++j) {
      const int idx = tid + (j << 7);
      const int r = idx >> 4, s = idx & 15;
      const int so = r * kAPad + s * 8;
      *(uint4*)(sma + so)          = *(const uint4*)(Qh + r * 128 + s * 8);
      *(uint4*)(sma + kATile + so) = *(const uint4*)(Ql + r * 128 + s * 8);
    }
  }
  __syncthreads();

  const uint32_t aAddr =
      base + 2u * (uint32_t)(((wid << 4) + (lane & 15)) * kAPad + ((lane >> 4) << 3));
  const uint32_t kAddr =
      base + 2u * kTileB +
      2u * (uint32_t)((lane & 15) * kAPad + ((lane >> 4) << 3));
  const uint32_t vAddr =
      base + 4u * kTileB +
      2u * (uint32_t)((lane & 15) * kAPad + ((lane >> 4) << 3));

  // ---- hoist Q fragments (loop-invariant) ----
  uint32_t qfh[8][4], qfl[8][4];
#pragma unroll
  for (int kc = 0; kc < 8; ++kc) {
    ldsm4(qfh[kc], aAddr + kc * 32);
    ldsm4(qfl[kc], aAddr + kc * 32 + kTileB);
  }

  float o[16][4];
#pragma unroll
  for (int t = 0; t < 16; ++t)
#pragma unroll
    for (int q = 0; q < 4; ++q) o[t][q] = 0.f;
  float mrun0 = -1e30f, mrun1 = -1e30f, lrun0 = 0.f, lrun1 = 0.f;

#pragma unroll 1
  for (int kb = 0; kb <= qb; ++kb) {
    __syncthreads();  // prior PV done before overwriting K/V smem
    const size_t kvoff = ((size_t)kvi * kT + ((size_t)kb << 6)) * kHD;
    // group 1: K hi/lo
#pragma unroll
    for (int j = 0; j < 8; ++j) {
      const int idx = tid + (j << 7);
      const int r = idx >> 4, s = idx & 15;
      const uint32_t so = (uint32_t)((r * kAPad + s * 8) * 2);
      const size_t go = kvoff + r * 128 + s * 8;
      cp16(base + 2u * kTileB + so, kh + go);
      cp16(base + 3u * kTileB + so, kl + go);
    }
    CP_COMMIT();
    // group 2: V hi/lo (overlaps S compute below)
#pragma unroll
    for (int j = 0; j < 8; ++j) {
      const int idx = tid + (j << 7);
      const int r = idx >> 4, s = idx & 15;
      const uint32_t so = (uint32_t)((r * kAPad + s * 8) * 2);
      const size_t go = kvoff + r * 128 + s * 8;
      cp16(base + 4u * kTileB + so, vh + go);
      cp16(base + 5u * kTileB + so, vl + go);
    }
    CP_COMMIT();

    CP_WAIT1();      // K arrived (V may still be in flight)
    __syncthreads();

    // ---- S = Q K^T (bf16x3) ----
    float sacc[8][4];
#pragma unroll
    for (int j = 0; j < 8; ++j)
#pragma unroll
      for (int q = 0; q < 4; ++q) sacc[j][q] = 0.f;

#pragma unroll
    for (int kc = 0; kc < 8; ++kc) {
#pragma unroll
      for (int p = 0; p < 4; ++p) {
        uint32_t bk[4], bkl_[4];
        const uint32_t bd = kAddr + (uint32_t)(p * 16 * kAPad * 2) + kc * 32;
        ldsm4(bk, bd);
        ldsm4(bkl_, bd + kTileB);
#pragma unroll
        for (int w2 = 0; w2 < 2; ++w2) {
          const int j = p * 2 + w2;
          mma_bf16(sacc[j], qfh[kc], bk[w2], bk[2 + w2]);
          mma_bf16(sacc[j], qfh[kc], bkl_[w2], bkl_[2 + w2]);
          mma_bf16(sacc[j], qfl[kc], bk[w2], bk[2 + w2]);
        }
      }
    }

    if (kb == qb) {
      const int r0 = (wid << 4) + g;
#pragma unroll
      for (int j = 0; j < 8; ++j) {
        const int c = (j << 3) + (t4 << 1);
        if (c > r0)         sacc[j][0] = -1e30f;
        if (c + 1 > r0)     sacc[j][1] = -1e30f;
        if (c > r0 + 8)     sacc[j][2] = -1e30f;
        if (c + 1 > r0 + 8) sacc[j][3] = -1e30f;
      }
    }

    // ---- online softmax in exp2 domain ----
    float mx0 = -1e30f, mx1 = -1e30f;
#pragma unroll
    for (int j = 0; j < 8; ++j) {
      mx0 = fmaxf(mx0, fmaxf(sacc[j][0], sacc[j][1]));
      mx1 = fmaxf(mx1, fmaxf(sacc[j][2], sacc[j][3]));
    }
    mx0 = fmaxf(mx0, __shfl_xor_sync(0xffffffffu, mx0, 1));
    mx0 = fmaxf(mx0, __shfl_xor_sync(0xffffffffu, mx0, 2));
    mx1 = fmaxf(mx1, __shfl_xor_sync(0xffffffffu, mx1, 1));
    mx1 = fmaxf(mx1, __shfl_xor_sync(0xffffffffu, mx1, 2));
    const float mn0 = fmaxf(mrun0, mx0), mn1 = fmaxf(mrun1, mx1);
    const float f0 = exp2f(mrun0 - mn0), f1 = exp2f(mrun1 - mn1);
    float rs0 = 0.f, rs1 = 0.f;
#pragma unroll
    for (int j = 0; j < 8; ++j) {
      sacc[j][0] = exp2f(sacc[j][0] - mn0);
      sacc[j][1] = exp2f(sacc[j][1] - mn0);
      sacc[j][2] = exp2f(sacc[j][2] - mn1);
      sacc[j][3] = exp2f(sacc[j][3] - mn1);
      rs0 += sacc[j][0] + sacc[j][1];
      rs1 += sacc[j][2] + sacc[j][3];
    }
    rs0 += __shfl_xor_sync(0xffffffffu, rs0, 1);
    rs0 += __shfl_xor_sync(0xffffffffu, rs0, 2);
    rs1 += __shfl_xor_sync(0xffffffffu, rs1, 1);
    rs1 += __shfl_xor_sync(0xffffffffu, rs1, 2);
    lrun0 = lrun0 * f0 + rs0;
    lrun1 = lrun1 * f1 + rs1;
    mrun0 = mn0;
    mrun1 = mn1;
#pragma unroll
    for (int t = 0; t < 16; ++t) {
      o[t][0] *= f0; o[t][1] *= f0; o[t][2] *= f1; o[t][3] *= f1;
    }

    // ---- P fragments: fp16, single term ----
    uint32_t pha[4][4];
#pragma unroll
    for (int jj = 0; jj < 4; ++jj) {
      pha[jj][0] = packh2(sacc[2 * jj][0], sacc[2 * jj][1]);
      pha[jj][1] = packh2(sacc[2 * jj][2], sacc[2 * jj][3]);
      pha[jj][2] = packh2(sacc[2 * jj + 1][0], sacc[2 * jj + 1][1]);
      pha[jj][3] = packh2(sacc[2 * jj + 1][2], sacc[2 * jj + 1][3]);
    }

    CP_WAIT0();      // V arrived
    __syncthreads();

    // ---- O += P V (fp16: P single x V hi/lo) ----
#pragma unroll
    for (int dc = 0; dc < 8; ++dc) {
#pragma unroll
      for (int jj = 0; jj < 4; ++jj) {
        uint32_t bv[4], bvl_[4];
        const uint32_t vd = vAddr + (uint32_t)(jj * 16 * kAPad * 2) + dc * 32;
        ldsm4t(bv, vd);
        ldsm4t(bvl_, vd + kTileB);
        mma_fp16(o[2 * dc], pha[jj], bv[0], bv[1]);
        mma_fp16(o[2 * dc], pha[jj], bvl_[0], bvl_[1]);
        mma_fp16(o[2 * dc + 1], pha[jj], bv[2], bv[3]);
        mma_fp16(o[2 * dc + 1], pha[jj], bvl_[2], bvl_[3]);
      }
    }
  }

  // ---- epilogue: normalize; write bf16 hi/lo as GEMM2's A ----
  const float i0 = 1.f / lrun0, i1 = 1.f / lrun1;
  const int row0 = q0 + (wid << 4) + g;
#pragma unroll
  for (int t = 0; t < 16; ++t) {
    const int d = (h << 7) + (t << 3) + (t4 << 1);
    uint32_t lo;
    uint32_t hi = packsplit(o[t][0] * i0, o[t][1] * i0, lo);
    *(uint32_t*)(oh + (size_t)row0 * kQS + d) = hi;
    *(uint32_t*)(ol + (size_t)row0 * kQS + d) = lo;
    hi = packsplit(o[t][2] * i1, o[t][3] * i1, lo);
    *(uint32_t*)(oh + (size_t)(row0 + 8) * kQS + d) = hi;
    *(uint32_t*)(ol + (size_t)(row0 + 8) * kQS + d) = lo;
  }
}

// =====================================================================
// launch — ordered so gemm_mma (QKV) is launch index 3 (ncu capture slot)
// =====================================================================
extern "C" void kernel_launch(void* const* d_in, const int* in_sizes, int n_in,
                              void* d_out, int out_size) {
  const int*   positions = (const int*)d_in[0];
  const float* hidden    = (const float*)d_in[1];
  const float* wqkv      = (const float*)d_in[2];
  const float* wo        = (const float*)d_in[3];
  float*       out       = (float*)d_out;

  void *p_qkv, *p_ah, *p_al, *p_b1h, *p_b1l, *p_b2h, *p_b2l;
  void *p_qh, *p_ql, *p_kh, *p_kl, *p_vh, *p_vl;
  cudaGetSymbolAddress(&p_qkv, g_qkv);
  cudaGetSymbolAddress(&p_ah, g_ah);
  cudaGetSymbolAddress(&p_al, g_al);
  cudaGetSymbolAddress(&p_b1h, g_b1h);
  cudaGetSymbolAddress(&p_b1l, g_b1l);
  cudaGetSymbolAddress(&p_b2h, g_b2h);
  cudaGetSymbolAddress(&p_b2l, g_b2l);
  cudaGetSymbolAddress(&p_qh, g_qh);
  cudaGetSymbolAddress(&p_ql, g_ql);
  cudaGetSymbolAddress(&p_kh, g_kh);
  cudaGetSymbolAddress(&p_kl, g_kl);
  cudaGetSymbolAddress(&p_vh, g_vh);
  cudaGetSymbolAddress(&p_vl, g_vl);

  float* qkv = (float*)p_qkv;
  __nv_bfloat16* ah = (__nv_bfloat16*)p_ah;
  __nv_bfloat16* al = (__nv_bfloat16*)p_al;
  __nv_bfloat16* b1h = (__nv_bfloat16*)p_b1h;
  __nv_bfloat16* b1l = (__nv_bfloat16*)p_b1l;
  __nv_bfloat16* b2h = (__nv_bfloat16*)p_b2h;
  __nv_bfloat16* b2l = (__nv_bfloat16*)p_b2l;
  __nv_bfloat16* qh = (__nv_bfloat16*)p_qh;
  __nv_bfloat16* ql = (__nv_bfloat16*)p_ql;
  __nv_bfloat16* kh = (__nv_bfloat16*)p_kh;
  __nv_bfloat16* kl = (__nv_bfloat16*)p_kl;
  __half* vh = (__half*)p_vh;
  __half* vl = (__half*)p_vl;

  constexpr int kAttnSmem = 6 * kATile * 2;  // 104448 B
  cudaFuncSetAttribute(attn_mma_kernel,
                       cudaFuncAttributeMaxDynamicSharedMemorySize, kAttnSmem);
  cudaFuncSetAttribute(gemm_mma_kernel,
                       cudaFuncAttributeMaxDynamicSharedMemorySize, kGemmSmem);

  // 0-2: conversions (transpose2 hoisted — dependency-free)
  split_kernel<<<kT * kH / 4 / 256, 256>>>(hidden, ah, al, kT * kH / 4);
  transpose_split_kernel<<<dim3(kQKV / 32, kH / 32), dim3(32, 8)>>>(
      wqkv, b1h, b1l, kH, kQKV);
  transpose_split_kernel<<<dim3(kQS / 32, kH / 32), dim3(32, 8)>>>(
      wo, b2h, b2l, kH, kQS);

  // 3: QKV projection GEMM (ncu capture slot)
  gemm_mma_kernel<<<dim3(kQKV / 128, kT / 128), 256, kGemmSmem>>>(
      ah, al, b1h, b1l, qkv, kQKV);

  // 4-5: RoPE fused with q/k split; V split
  const int ropeTot = kT * (kNH + kNKV) * 64;
  rope_split_kernel<<<(ropeTot + 255) / 256, 256>>>(positions, qkv, qh, ql, kh, kl);
  vsplit_kernel<<<kT * 1024 / 4 / 256, 256>>>(qkv, vh, vl);

  // 6: attention (writes GEMM2's A hi/lo directly)
  attn_mma_kernel<<<dim3(kNH, kT / 64), 128, kAttnSmem>>>(
      qh, ql, kh, kl, vh, vl, ah, al);

  // 7: output projection
  gemm_mma_kernel<<<dim3(kQS / 128, kT / 128), 256, kGemmSmem>>>(
      ah, al, b2h, b2l, out, kQS);
}